// round 1
// baseline (speedup 1.0000x reference)
#include <cuda_runtime.h>
#include <cuda_bf16.h>
#include <math.h>

// Problem constants (fixed-shape problem)
#define NN      50000
#define EE      800000
#define ETOT    (EE + NN)      // self-loops appended
#define IN_CH   512
#define HID     32
#define HEADS   8
#define D1      (HID * HEADS)  // 256
#define NCLS    40
#define NEG_SLOPE 0.2f

// ---------------- scratch (device globals, no allocs allowed) ----------------
__device__ __align__(128) float g_h1[NN * D1];       // 51.2 MB
__device__ __align__(128) float g_out1[NN * D1];     // 51.2 MB (agg result, then ELU'd)
__device__ __align__(128) float g_p[ETOT * HEADS];   // 27.2 MB
__device__ __align__(128) float g_al_src[NN * HEADS];
__device__ __align__(128) float g_al_dst[NN * HEADS];
__device__ __align__(128) float g_denom[NN * HEADS];
__device__ __align__(128) float g_h2[NN * NCLS];     // 8 MB
__device__ __align__(128) float g_p2[ETOT];
__device__ __align__(128) float g_al2s[NN];
__device__ __align__(128) float g_al2d[NN];
__device__ __align__(128) float g_denom2[NN];

// ---------------- helpers ----------------
__device__ __forceinline__ void red_add_v4(float* addr, float4 v) {
    asm volatile("red.global.add.v4.f32 [%0], {%1, %2, %3, %4};"
                 :: "l"(addr), "f"(v.x), "f"(v.y), "f"(v.z), "f"(v.w)
                 : "memory");
}

__device__ __forceinline__ float leaky(float x) {
    return x > 0.0f ? x : NEG_SLOPE * x;
}

// ---------------- SGEMM 128x128x8, 256 threads, 8x8 per thread ----------------
__global__ __launch_bounds__(256)
void sgemm128(const float* __restrict__ A, const float* __restrict__ B,
              float* __restrict__ C, int M, int N, int K) {
    __shared__ float As[8][128];
    __shared__ float Bs[8][128];
    int tid = threadIdx.x;
    int br = blockIdx.y;
    int bc = blockIdx.x;

    const float* Ab = A + (size_t)br * 128 * K;
    const float* Bb = B + bc * 128;

    float acc[8][8];
#pragma unroll
    for (int i = 0; i < 8; i++)
#pragma unroll
        for (int j = 0; j < 8; j++) acc[i][j] = 0.0f;

    int aRow = tid >> 1;            // 0..127
    int aCol = (tid & 1) * 4;       // 0 or 4
    int bRow = tid >> 5;            // 0..7
    int bCol = (tid & 31) * 4;      // 0..124
    int tr = (tid >> 4) * 8;        // 0..120
    int tc = (tid & 15) * 8;        // 0..120
    int gRowA = br * 128 + aRow;

    for (int k0 = 0; k0 < K; k0 += 8) {
        float4 av = make_float4(0.f, 0.f, 0.f, 0.f);
        if (gRowA < M)
            av = *reinterpret_cast<const float4*>(Ab + (size_t)aRow * K + k0 + aCol);
        As[aCol + 0][aRow] = av.x;
        As[aCol + 1][aRow] = av.y;
        As[aCol + 2][aRow] = av.z;
        As[aCol + 3][aRow] = av.w;

        float4 bv = *reinterpret_cast<const float4*>(Bb + (size_t)(k0 + bRow) * N + bCol);
        *reinterpret_cast<float4*>(&Bs[bRow][bCol]) = bv;
        __syncthreads();

#pragma unroll
        for (int kk = 0; kk < 8; kk++) {
            float ra[8], rb[8];
#pragma unroll
            for (int i = 0; i < 8; i++) ra[i] = As[kk][tr + i];
#pragma unroll
            for (int j = 0; j < 8; j++) rb[j] = Bs[kk][tc + j];
#pragma unroll
            for (int i = 0; i < 8; i++)
#pragma unroll
                for (int j = 0; j < 8; j++) acc[i][j] += ra[i] * rb[j];
        }
        __syncthreads();
    }

#pragma unroll
    for (int i = 0; i < 8; i++) {
        int gRow = br * 128 + tr + i;
        if (gRow < M) {
#pragma unroll
            for (int j = 0; j < 8; j += 4) {
                float4 v = make_float4(acc[i][j], acc[i][j + 1], acc[i][j + 2], acc[i][j + 3]);
                *reinterpret_cast<float4*>(C + (size_t)gRow * N + bc * 128 + tc + j) = v;
            }
        }
    }
}

// ---------------- per-node attention dots, layer 1 ----------------
__global__ void al1_kernel(const float* __restrict__ att_src,
                           const float* __restrict__ att_dst) {
    int idx = blockIdx.x * blockDim.x + threadIdx.x;
    if (idx >= NN * HEADS) return;
    int n = idx >> 3;
    int h = idx & 7;
    const float* row = g_h1 + (size_t)n * D1 + h * HID;
    const float* as = att_src + h * HID;
    const float* ad = att_dst + h * HID;
    float s = 0.f, d = 0.f;
#pragma unroll
    for (int c = 0; c < HID; c++) {
        float v = row[c];
        s += v * as[c];
        d += v * ad[c];
    }
    g_al_src[idx] = s;
    g_al_dst[idx] = d;
}

// ---------------- zero / init ----------------
__global__ void zero_kernel(float* p, int n) {
    int i = blockIdx.x * blockDim.x + threadIdx.x;
    if (i < n) p[i] = 0.0f;
}

__global__ void init_out_kernel(float* out, const float* __restrict__ b2) {
    int i = blockIdx.x * blockDim.x + threadIdx.x;
    if (i < NN * NCLS) out[i] = b2[i % NCLS];
}

// ---------------- edge pass 1 ----------------
__global__ void edge1_kernel(const int* __restrict__ ei) {
    int e = blockIdx.x * blockDim.x + threadIdx.x;
    if (e >= ETOT) return;
    int src, dst;
    if (e < EE) { src = ei[e]; dst = ei[EE + e]; }
    else        { src = dst = e - EE; }

    const float4* s4 = reinterpret_cast<const float4*>(g_al_src + (size_t)src * 8);
    const float4* d4 = reinterpret_cast<const float4*>(g_al_dst + (size_t)dst * 8);
    float4 s0 = s4[0], s1 = s4[1];
    float4 d0 = d4[0], d1 = d4[1];

    float4 p0, p1;
    p0.x = __expf(leaky(s0.x + d0.x));
    p0.y = __expf(leaky(s0.y + d0.y));
    p0.z = __expf(leaky(s0.z + d0.z));
    p0.w = __expf(leaky(s0.w + d0.w));
    p1.x = __expf(leaky(s1.x + d1.x));
    p1.y = __expf(leaky(s1.y + d1.y));
    p1.z = __expf(leaky(s1.z + d1.z));
    p1.w = __expf(leaky(s1.w + d1.w));

    float4* pp = reinterpret_cast<float4*>(g_p + (size_t)e * 8);
    pp[0] = p0;
    pp[1] = p1;
    red_add_v4(g_denom + (size_t)dst * 8, p0);
    red_add_v4(g_denom + (size_t)dst * 8 + 4, p1);
}

// ---------------- aggregation 1: out1[dst] += h1[src] * alpha ----------------
__global__ __launch_bounds__(256)
void agg1_kernel(const int* __restrict__ ei) {
    int gid = blockIdx.x * 256 + threadIdx.x;
    int e = gid >> 6;        // 64 threads per edge
    int sub = gid & 63;      // float4 group -> channels [sub*4, sub*4+4)
    if (e >= ETOT) return;
    int src, dst;
    if (e < EE) { src = ei[e]; dst = ei[EE + e]; }
    else        { src = dst = e - EE; }

    int head = sub >> 3;     // (sub*4)/32
    float alpha = g_p[(size_t)e * 8 + head] /
                  (g_denom[(size_t)dst * 8 + head] + 1e-16f);

    float4 v = reinterpret_cast<const float4*>(g_h1 + (size_t)src * D1)[sub];
    v.x *= alpha; v.y *= alpha; v.z *= alpha; v.w *= alpha;
    red_add_v4(g_out1 + (size_t)dst * D1 + sub * 4, v);
}

// ---------------- bias + ELU (in place on g_out1) ----------------
__global__ void elu_kernel(const float* __restrict__ b1) {
    int i = blockIdx.x * blockDim.x + threadIdx.x;
    if (i >= NN * D1) return;
    float v = g_out1[i] + b1[i & (D1 - 1)];
    g_out1[i] = v > 0.0f ? v : expm1f(v);
}

// ---------------- GEMM2: h2 = elu(out1) @ W2  [50000,256]x[256,40] ----------------
__global__ void gemm2_kernel(const float* __restrict__ W2) {
    int idx = blockIdx.x * blockDim.x + threadIdx.x;
    if (idx >= NN * NCLS) return;
    int n = idx / NCLS;
    int j = idx - n * NCLS;
    const float* a = g_out1 + (size_t)n * D1;
    float s = 0.0f;
#pragma unroll 8
    for (int k = 0; k < D1; k++)
        s += a[k] * W2[k * NCLS + j];
    g_h2[idx] = s;
}

// ---------------- per-node attention dots, layer 2 ----------------
__global__ void al2_kernel(const float* __restrict__ att_src2,
                           const float* __restrict__ att_dst2) {
    int n = blockIdx.x * blockDim.x + threadIdx.x;
    if (n >= NN) return;
    const float* row = g_h2 + (size_t)n * NCLS;
    float s = 0.f, d = 0.f;
#pragma unroll
    for (int j = 0; j < NCLS; j++) {
        float v = row[j];
        s += v * att_src2[j];
        d += v * att_dst2[j];
    }
    g_al2s[n] = s;
    g_al2d[n] = d;
}

// ---------------- edge pass 2 ----------------
__global__ void edge2_kernel(const int* __restrict__ ei) {
    int e = blockIdx.x * blockDim.x + threadIdx.x;
    if (e >= ETOT) return;
    int src, dst;
    if (e < EE) { src = ei[e]; dst = ei[EE + e]; }
    else        { src = dst = e - EE; }
    float p = __expf(leaky(g_al2s[src] + g_al2d[dst]));
    g_p2[e] = p;
    atomicAdd(g_denom2 + dst, p);
}

// ---------------- aggregation 2: d_out[dst] += h2[src] * alpha2 ----------------
__global__ void agg2_kernel(const int* __restrict__ ei, float* __restrict__ out) {
    int idx = blockIdx.x * blockDim.x + threadIdx.x;
    if (idx >= ETOT * 10) return;       // 10 float4 groups per edge (40 ch)
    int e = idx / 10;
    int g = idx - e * 10;
    int src, dst;
    if (e < EE) { src = ei[e]; dst = ei[EE + e]; }
    else        { src = dst = e - EE; }
    float alpha = g_p2[e] / (g_denom2[dst] + 1e-16f);
    float4 v = reinterpret_cast<const float4*>(g_h2 + (size_t)src * NCLS)[g];
    v.x *= alpha; v.y *= alpha; v.z *= alpha; v.w *= alpha;
    red_add_v4(out + (size_t)dst * NCLS + g * 4, v);
}

// ---------------- launch ----------------
extern "C" void kernel_launch(void* const* d_in, const int* in_sizes, int n_in,
                              void* d_out, int out_size) {
    const float* x        = (const float*)d_in[0];
    const int*   ei       = (const int*)  d_in[1];
    const float* W1       = (const float*)d_in[2];
    const float* att_src1 = (const float*)d_in[3];
    const float* att_dst1 = (const float*)d_in[4];
    const float* b1       = (const float*)d_in[5];
    const float* W2       = (const float*)d_in[6];
    const float* att_src2 = (const float*)d_in[7];
    const float* att_dst2 = (const float*)d_in[8];
    const float* b2       = (const float*)d_in[9];
    float* out = (float*)d_out;

    float *p_denom, *p_out1, *p_denom2, *p_h1;
    cudaGetSymbolAddress((void**)&p_denom,  g_denom);
    cudaGetSymbolAddress((void**)&p_out1,   g_out1);
    cudaGetSymbolAddress((void**)&p_denom2, g_denom2);
    cudaGetSymbolAddress((void**)&p_h1,     g_h1);

    // 1. GEMM1: h1 = x @ W1  [50000,512]x[512,256]
    {
        dim3 grid(D1 / 128, (NN + 127) / 128);
        sgemm128<<<grid, 256>>>(x, W1, p_h1, NN, D1, IN_CH);
    }

    // 2. attention dots layer 1
    al1_kernel<<<(NN * HEADS + 255) / 256, 256>>>(att_src1, att_dst1);

    // 3. init scratch + output
    zero_kernel<<<(NN * HEADS + 255) / 256, 256>>>(p_denom, NN * HEADS);
    zero_kernel<<<(NN * D1 + 255) / 256, 256>>>(p_out1, NN * D1);
    zero_kernel<<<(NN + 255) / 256, 256>>>(p_denom2, NN);
    init_out_kernel<<<(NN * NCLS + 255) / 256, 256>>>(out, b2);

    // 4. edge softmax numerators + denominators (layer 1)
    edge1_kernel<<<(ETOT + 255) / 256, 256>>>(ei);

    // 5. aggregation layer 1 (64 threads / edge)
    agg1_kernel<<<(ETOT * 64 + 255) / 256, 256>>>(ei);

    // 6. bias + ELU
    elu_kernel<<<(NN * D1 + 255) / 256, 256>>>(b1);

    // 7. GEMM2
    gemm2_kernel<<<(NN * NCLS + 255) / 256, 256>>>(W2);

    // 8. attention dots layer 2
    al2_kernel<<<(NN + 255) / 256, 256>>>(att_src2, att_dst2);

    // 9. edge softmax layer 2
    edge2_kernel<<<(ETOT + 255) / 256, 256>>>(ei);

    // 10. aggregation layer 2 -> d_out
    agg2_kernel<<<(ETOT * 10 + 255) / 256, 256>>>(ei, out);
}

// round 2
// speedup vs baseline: 1.5273x; 1.5273x over previous
#include <cuda_runtime.h>
#include <cuda_bf16.h>
#include <math.h>
#include <stdint.h>

// Problem constants (fixed-shape problem)
#define NN      50000
#define EE      800000
#define ETOT    (EE + NN)      // self-loops appended
#define IN_CH   512
#define HID     32
#define HEADS   8
#define D1      (HID * HEADS)  // 256
#define NCLS    40
#define NEG_SLOPE 0.2f

// ---------------- scratch (device globals, no allocs allowed) ----------------
__device__ __align__(128) float g_h1[NN * D1];       // 51.2 MB
__device__ __align__(128) float g_out1[NN * D1];     // 51.2 MB (agg result, then ELU'd)
__device__ __align__(128) float g_p[ETOT * HEADS];   // 27.2 MB
__device__ __align__(128) float g_al_src[NN * HEADS];
__device__ __align__(128) float g_al_dst[NN * HEADS];
__device__ __align__(128) float g_denom[NN * HEADS];
__device__ __align__(128) float g_h2[NN * NCLS];     // 8 MB
__device__ __align__(128) float g_p2[ETOT];
__device__ __align__(128) float g_al2s[NN];
__device__ __align__(128) float g_al2d[NN];
__device__ __align__(128) float g_denom2[NN];

// ---------------- helpers ----------------
__device__ __forceinline__ void red_add_v4(float* addr, float4 v) {
    asm volatile("red.global.add.v4.f32 [%0], {%1, %2, %3, %4};"
                 :: "l"(addr), "f"(v.x), "f"(v.y), "f"(v.z), "f"(v.w)
                 : "memory");
}

__device__ __forceinline__ float leaky(float x) {
    return x > 0.0f ? x : NEG_SLOPE * x;
}

__device__ __forceinline__ uint32_t f2tf32(float f) {
    uint32_t r;
    asm("cvt.rn.tf32.f32 %0, %1;" : "=r"(r) : "f"(f));
    return r;
}

__device__ __forceinline__ void mma_tf32(float c[4], uint32_t a0, uint32_t a1,
                                         uint32_t a2, uint32_t a3,
                                         uint32_t b0, uint32_t b1) {
    asm volatile(
        "mma.sync.aligned.m16n8k8.row.col.f32.tf32.tf32.f32 "
        "{%0,%1,%2,%3}, {%4,%5,%6,%7}, {%8,%9}, {%0,%1,%2,%3};\n"
        : "+f"(c[0]), "+f"(c[1]), "+f"(c[2]), "+f"(c[3])
        : "r"(a0), "r"(a1), "r"(a2), "r"(a3), "r"(b0), "r"(b1));
}

// =====================================================================
// tf32 tensor-core GEMM: C[M,N] = A[M,K] @ B[K,N], row-major.
// Block tile BM x BN, 8 warps (WARPS_M x WARPS_N), warp tile 32 x 64.
// K consumed in chunks of 32. Bank-conflict-free smem:
//   As[m][36]      (32 k + 4 pad)   frag bank = (4g + t + 8ks) distinct
//   Bs[k][BN+8]    frag bank = 8(t+ni) + g distinct
// =====================================================================
template <int BM, int BN, int WARPS_M, int NCOLS, int KTOT>
__global__ __launch_bounds__(256)
void tf32_gemm(const float* __restrict__ A, const float* __restrict__ B,
               float* __restrict__ C, int M) {
    constexpr int APAD = 36;
    constexpr int BPAD = BN + 8;
    __shared__ uint32_t As[BM][APAD];
    __shared__ uint32_t Bs[32][BPAD];

    const int tid = threadIdx.x;
    const int lane = tid & 31;
    const int warpId = tid >> 5;
    const int br = blockIdx.y;
    const int bc = blockIdx.x;

    const int wm = (warpId % WARPS_M) * 32;
    const int wn = (warpId / WARPS_M) * 64;
    const int g = lane >> 2;       // groupID 0..7
    const int t = lane & 3;        // threadID_in_group 0..3

    float acc[2][8][4];
#pragma unroll
    for (int mi = 0; mi < 2; mi++)
#pragma unroll
        for (int ni = 0; ni < 8; ni++)
#pragma unroll
            for (int r = 0; r < 4; r++) acc[mi][ni][r] = 0.0f;

    // A loader indices: warp reads 4 rows x 32 k (coalesced 128B/row)
    const int a_m = tid >> 3;            // 0..31 (row within 32-row group)
    const int a_k = (tid & 7) * 4;       // 0,4,...,28
    // B loader indices
    constexpr int TPR = BN / 4;          // threads per B row
    constexpr int BROWS = 256 / TPR;     // rows per pass
    constexpr int BITER = 32 / BROWS;
    const int b_n = (tid % TPR) * 4;
    const int b_k = tid / TPR;

    for (int k0 = 0; k0 < KTOT; k0 += 32) {
        // ---- load A chunk [BM x 32] ----
#pragma unroll
        for (int r = 0; r < BM / 32; r++) {
            int m = r * 32 + a_m;
            int grow = br * BM + m;
            float4 v = make_float4(0.f, 0.f, 0.f, 0.f);
            if (grow < M)
                v = *reinterpret_cast<const float4*>(A + (size_t)grow * KTOT + k0 + a_k);
            uint4 u;
            u.x = f2tf32(v.x); u.y = f2tf32(v.y);
            u.z = f2tf32(v.z); u.w = f2tf32(v.w);
            *reinterpret_cast<uint4*>(&As[m][a_k]) = u;
        }
        // ---- load B chunk [32 x BN] ----
#pragma unroll
        for (int r = 0; r < BITER; r++) {
            int k = r * BROWS + b_k;
            int gn = bc * BN + b_n;
            float4 v = make_float4(0.f, 0.f, 0.f, 0.f);
            if (gn < NCOLS)
                v = *reinterpret_cast<const float4*>(B + (size_t)(k0 + k) * NCOLS + gn);
            uint4 u;
            u.x = f2tf32(v.x); u.y = f2tf32(v.y);
            u.z = f2tf32(v.z); u.w = f2tf32(v.w);
            *reinterpret_cast<uint4*>(&Bs[k][b_n]) = u;
        }
        __syncthreads();

        // ---- compute: 4 k-steps of 8 ----
#pragma unroll
        for (int ks = 0; ks < 4; ks++) {
            const int kk = ks * 8;
            uint32_t a[2][4];
#pragma unroll
            for (int mi = 0; mi < 2; mi++) {
                int m0 = wm + mi * 16 + g;
                a[mi][0] = As[m0][kk + t];
                a[mi][1] = As[m0 + 8][kk + t];
                a[mi][2] = As[m0][kk + t + 4];
                a[mi][3] = As[m0 + 8][kk + t + 4];
            }
#pragma unroll
            for (int ni = 0; ni < 8; ni++) {
                int n0 = wn + ni * 8 + g;
                uint32_t b0 = Bs[kk + t][n0];
                uint32_t b1 = Bs[kk + t + 4][n0];
                mma_tf32(acc[0][ni], a[0][0], a[0][1], a[0][2], a[0][3], b0, b1);
                mma_tf32(acc[1][ni], a[1][0], a[1][1], a[1][2], a[1][3], b0, b1);
            }
        }
        __syncthreads();
    }

    // ---- epilogue ----
#pragma unroll
    for (int mi = 0; mi < 2; mi++) {
        int row0 = br * BM + wm + mi * 16 + g;
        int row1 = row0 + 8;
#pragma unroll
        for (int ni = 0; ni < 8; ni++) {
            int col = bc * BN + wn + ni * 8 + 2 * t;
            if (col < NCOLS) {
                if (row0 < M) {
                    float2 v = make_float2(acc[mi][ni][0], acc[mi][ni][1]);
                    *reinterpret_cast<float2*>(C + (size_t)row0 * NCOLS + col) = v;
                }
                if (row1 < M) {
                    float2 v = make_float2(acc[mi][ni][2], acc[mi][ni][3]);
                    *reinterpret_cast<float2*>(C + (size_t)row1 * NCOLS + col) = v;
                }
            }
        }
    }
}

// ---------------- per-node attention dots, layer 1 ----------------
__global__ void al1_kernel(const float* __restrict__ att_src,
                           const float* __restrict__ att_dst) {
    int idx = blockIdx.x * blockDim.x + threadIdx.x;
    if (idx >= NN * HEADS) return;
    int n = idx >> 3;
    int h = idx & 7;
    const float* row = g_h1 + (size_t)n * D1 + h * HID;
    const float* as = att_src + h * HID;
    const float* ad = att_dst + h * HID;
    float s = 0.f, d = 0.f;
#pragma unroll
    for (int c = 0; c < HID; c++) {
        float v = row[c];
        s += v * as[c];
        d += v * ad[c];
    }
    g_al_src[idx] = s;
    g_al_dst[idx] = d;
}

// ---------------- zero / init ----------------
__global__ void zero_kernel(float* p, int n) {
    int i = blockIdx.x * blockDim.x + threadIdx.x;
    if (i < n) p[i] = 0.0f;
}

__global__ void init_out_kernel(float* out, const float* __restrict__ b2) {
    int i = blockIdx.x * blockDim.x + threadIdx.x;
    if (i < NN * NCLS) out[i] = b2[i % NCLS];
}

// ---------------- edge pass 1 ----------------
__global__ void edge1_kernel(const int* __restrict__ ei) {
    int e = blockIdx.x * blockDim.x + threadIdx.x;
    if (e >= ETOT) return;
    int src, dst;
    if (e < EE) { src = ei[e]; dst = ei[EE + e]; }
    else        { src = dst = e - EE; }

    const float4* s4 = reinterpret_cast<const float4*>(g_al_src + (size_t)src * 8);
    const float4* d4 = reinterpret_cast<const float4*>(g_al_dst + (size_t)dst * 8);
    float4 s0 = s4[0], s1 = s4[1];
    float4 d0 = d4[0], d1 = d4[1];

    float4 p0, p1;
    p0.x = __expf(leaky(s0.x + d0.x));
    p0.y = __expf(leaky(s0.y + d0.y));
    p0.z = __expf(leaky(s0.z + d0.z));
    p0.w = __expf(leaky(s0.w + d0.w));
    p1.x = __expf(leaky(s1.x + d1.x));
    p1.y = __expf(leaky(s1.y + d1.y));
    p1.z = __expf(leaky(s1.z + d1.z));
    p1.w = __expf(leaky(s1.w + d1.w));

    float4* pp = reinterpret_cast<float4*>(g_p + (size_t)e * 8);
    pp[0] = p0;
    pp[1] = p1;
    red_add_v4(g_denom + (size_t)dst * 8, p0);
    red_add_v4(g_denom + (size_t)dst * 8 + 4, p1);
}

// ---------------- aggregation 1: out1[dst] += h1[src] * alpha ----------------
__global__ __launch_bounds__(256)
void agg1_kernel(const int* __restrict__ ei) {
    int gid = blockIdx.x * 256 + threadIdx.x;
    int e = gid >> 6;        // 64 threads per edge
    int sub = gid & 63;      // float4 group -> channels [sub*4, sub*4+4)
    if (e >= ETOT) return;
    int src, dst;
    if (e < EE) { src = ei[e]; dst = ei[EE + e]; }
    else        { src = dst = e - EE; }

    int head = sub >> 3;     // (sub*4)/32
    float alpha = g_p[(size_t)e * 8 + head] /
                  (g_denom[(size_t)dst * 8 + head] + 1e-16f);

    float4 v = reinterpret_cast<const float4*>(g_h1 + (size_t)src * D1)[sub];
    v.x *= alpha; v.y *= alpha; v.z *= alpha; v.w *= alpha;
    red_add_v4(g_out1 + (size_t)dst * D1 + sub * 4, v);
}

// ---------------- bias + ELU (in place on g_out1) ----------------
__global__ void elu_kernel(const float* __restrict__ b1) {
    int i = blockIdx.x * blockDim.x + threadIdx.x;
    if (i >= NN * D1) return;
    float v = g_out1[i] + b1[i & (D1 - 1)];
    g_out1[i] = v > 0.0f ? v : expm1f(v);
}

// ---------------- per-node attention dots, layer 2 ----------------
__global__ void al2_kernel(const float* __restrict__ att_src2,
                           const float* __restrict__ att_dst2) {
    int n = blockIdx.x * blockDim.x + threadIdx.x;
    if (n >= NN) return;
    const float* row = g_h2 + (size_t)n * NCLS;
    float s = 0.f, d = 0.f;
#pragma unroll
    for (int j = 0; j < NCLS; j++) {
        float v = row[j];
        s += v * att_src2[j];
        d += v * att_dst2[j];
    }
    g_al2s[n] = s;
    g_al2d[n] = d;
}

// ---------------- edge pass 2 ----------------
__global__ void edge2_kernel(const int* __restrict__ ei) {
    int e = blockIdx.x * blockDim.x + threadIdx.x;
    if (e >= ETOT) return;
    int src, dst;
    if (e < EE) { src = ei[e]; dst = ei[EE + e]; }
    else        { src = dst = e - EE; }
    float p = __expf(leaky(g_al2s[src] + g_al2d[dst]));
    g_p2[e] = p;
    atomicAdd(g_denom2 + dst, p);
}

// ---------------- aggregation 2: d_out[dst] += h2[src] * alpha2 ----------------
__global__ void agg2_kernel(const int* __restrict__ ei, float* __restrict__ out) {
    int idx = blockIdx.x * blockDim.x + threadIdx.x;
    if (idx >= ETOT * 10) return;       // 10 float4 groups per edge (40 ch)
    int e = idx / 10;
    int g = idx - e * 10;
    int src, dst;
    if (e < EE) { src = ei[e]; dst = ei[EE + e]; }
    else        { src = dst = e - EE; }
    float alpha = g_p2[e] / (g_denom2[dst] + 1e-16f);
    float4 v = reinterpret_cast<const float4*>(g_h2 + (size_t)src * NCLS)[g];
    v.x *= alpha; v.y *= alpha; v.z *= alpha; v.w *= alpha;
    red_add_v4(out + (size_t)dst * NCLS + g * 4, v);
}

// ---------------- launch ----------------
extern "C" void kernel_launch(void* const* d_in, const int* in_sizes, int n_in,
                              void* d_out, int out_size) {
    const float* x        = (const float*)d_in[0];
    const int*   ei       = (const int*)  d_in[1];
    const float* W1       = (const float*)d_in[2];
    const float* att_src1 = (const float*)d_in[3];
    const float* att_dst1 = (const float*)d_in[4];
    const float* b1       = (const float*)d_in[5];
    const float* W2       = (const float*)d_in[6];
    const float* att_src2 = (const float*)d_in[7];
    const float* att_dst2 = (const float*)d_in[8];
    const float* b2       = (const float*)d_in[9];
    float* out = (float*)d_out;

    float *p_denom, *p_out1, *p_denom2, *p_h1, *p_h2;
    cudaGetSymbolAddress((void**)&p_denom,  g_denom);
    cudaGetSymbolAddress((void**)&p_out1,   g_out1);
    cudaGetSymbolAddress((void**)&p_denom2, g_denom2);
    cudaGetSymbolAddress((void**)&p_h1,     g_h1);
    cudaGetSymbolAddress((void**)&p_h2,     g_h2);

    // 1. GEMM1 (tf32 tensor cores): h1 = x @ W1  [50000,512]x[512,256]
    {
        dim3 grid(D1 / 128, (NN + 127) / 128);   // (2, 391)
        tf32_gemm<128, 128, 4, D1, IN_CH><<<grid, 256>>>(x, W1, p_h1, NN);
    }

    // 2. attention dots layer 1
    al1_kernel<<<(NN * HEADS + 255) / 256, 256>>>(att_src1, att_dst1);

    // 3. init scratch + output
    zero_kernel<<<(NN * HEADS + 255) / 256, 256>>>(p_denom, NN * HEADS);
    zero_kernel<<<(NN * D1 + 255) / 256, 256>>>(p_out1, NN * D1);
    zero_kernel<<<(NN + 255) / 256, 256>>>(p_denom2, NN);
    init_out_kernel<<<(NN * NCLS + 255) / 256, 256>>>(out, b2);

    // 4. edge softmax numerators + denominators (layer 1)
    edge1_kernel<<<(ETOT + 255) / 256, 256>>>(ei);

    // 5. aggregation layer 1 (64 threads / edge)
    agg1_kernel<<<(ETOT * 64 + 255) / 256, 256>>>(ei);

    // 6. bias + ELU
    elu_kernel<<<(NN * D1 + 255) / 256, 256>>>(b1);

    // 7. GEMM2 (tf32 tensor cores): h2 = elu(out1) @ W2  [50000,256]x[256,40]
    {
        dim3 grid(1, (NN + 255) / 256);          // (1, 196)
        tf32_gemm<256, 64, 8, NCLS, D1><<<grid, 256>>>(p_out1, W2, p_h2, NN);
    }

    // 8. attention dots layer 2
    al2_kernel<<<(NN + 255) / 256, 256>>>(att_src2, att_dst2);

    // 9. edge softmax layer 2
    edge2_kernel<<<(ETOT + 255) / 256, 256>>>(ei);

    // 10. aggregation layer 2 -> d_out
    agg2_kernel<<<(ETOT * 10 + 255) / 256, 256>>>(ei, out);
}

// round 3
// speedup vs baseline: 2.7787x; 1.8193x over previous
#include <cuda_runtime.h>
#include <cuda_bf16.h>
#include <math.h>
#include <stdint.h>

// Problem constants (fixed-shape problem)
#define NN      50000
#define EE      800000
#define ETOT    (EE + NN)      // self-loops appended
#define IN_CH   512
#define HID     32
#define HEADS   8
#define D1      (HID * HEADS)  // 256
#define NCLS    40
#define NEG_SLOPE 0.2f
#define NB_SCAN ((NN + 255) / 256)   // 196

// ---------------- scratch (device globals, no allocs allowed) ----------------
__device__ __align__(128) float g_h1[NN * D1];       // 51.2 MB
__device__ __align__(128) float g_out1[NN * D1];     // 51.2 MB (post-ELU)
__device__ __align__(128) float g_al_src[NN * HEADS];
__device__ __align__(128) float g_al_dst[NN * HEADS];
__device__ __align__(128) float g_h2[NN * NCLS];     // 8 MB
__device__ __align__(128) float g_al2s[NN];
__device__ __align__(128) float g_al2d[NN];
// CSR-by-dst
__device__ int g_deg[NN];
__device__ int g_off[NN];
__device__ int g_wpos[NN];
__device__ int g_esrc[ETOT];
__device__ int g_bsum[NB_SCAN];
__device__ int g_bsumx[NB_SCAN];

// ---------------- helpers ----------------
__device__ __forceinline__ float leaky(float x) {
    return x > 0.0f ? x : NEG_SLOPE * x;
}

__device__ __forceinline__ uint32_t f2tf32(float f) {
    uint32_t r;
    asm("cvt.rn.tf32.f32 %0, %1;" : "=r"(r) : "f"(f));
    return r;
}

__device__ __forceinline__ void mma_tf32(float c[4], uint32_t a0, uint32_t a1,
                                         uint32_t a2, uint32_t a3,
                                         uint32_t b0, uint32_t b1) {
    asm volatile(
        "mma.sync.aligned.m16n8k8.row.col.f32.tf32.tf32.f32 "
        "{%0,%1,%2,%3}, {%4,%5,%6,%7}, {%8,%9}, {%0,%1,%2,%3};\n"
        : "+f"(c[0]), "+f"(c[1]), "+f"(c[2]), "+f"(c[3])
        : "r"(a0), "r"(a1), "r"(a2), "r"(a3), "r"(b0), "r"(b1));
}

// =====================================================================
// tf32 tensor-core GEMM: C[M,N] = A[M,K] @ B[K,N], row-major.
// =====================================================================
template <int BM, int BN, int WARPS_M, int NCOLS, int KTOT>
__global__ __launch_bounds__(256)
void tf32_gemm(const float* __restrict__ A, const float* __restrict__ B,
               float* __restrict__ C, int M) {
    constexpr int APAD = 36;
    constexpr int BPAD = BN + 8;
    __shared__ uint32_t As[BM][APAD];
    __shared__ uint32_t Bs[32][BPAD];

    const int tid = threadIdx.x;
    const int lane = tid & 31;
    const int warpId = tid >> 5;
    const int br = blockIdx.y;
    const int bc = blockIdx.x;

    const int wm = (warpId % WARPS_M) * 32;
    const int wn = (warpId / WARPS_M) * 64;
    const int g = lane >> 2;
    const int t = lane & 3;

    float acc[2][8][4];
#pragma unroll
    for (int mi = 0; mi < 2; mi++)
#pragma unroll
        for (int ni = 0; ni < 8; ni++)
#pragma unroll
            for (int r = 0; r < 4; r++) acc[mi][ni][r] = 0.0f;

    const int a_m = tid >> 3;
    const int a_k = (tid & 7) * 4;
    constexpr int TPR = BN / 4;
    constexpr int BROWS = 256 / TPR;
    constexpr int BITER = 32 / BROWS;
    const int b_n = (tid % TPR) * 4;
    const int b_k = tid / TPR;

    for (int k0 = 0; k0 < KTOT; k0 += 32) {
#pragma unroll
        for (int r = 0; r < BM / 32; r++) {
            int m = r * 32 + a_m;
            int grow = br * BM + m;
            float4 v = make_float4(0.f, 0.f, 0.f, 0.f);
            if (grow < M)
                v = *reinterpret_cast<const float4*>(A + (size_t)grow * KTOT + k0 + a_k);
            uint4 u;
            u.x = f2tf32(v.x); u.y = f2tf32(v.y);
            u.z = f2tf32(v.z); u.w = f2tf32(v.w);
            *reinterpret_cast<uint4*>(&As[m][a_k]) = u;
        }
#pragma unroll
        for (int r = 0; r < BITER; r++) {
            int k = r * BROWS + b_k;
            int gn = bc * BN + b_n;
            float4 v = make_float4(0.f, 0.f, 0.f, 0.f);
            if (gn < NCOLS)
                v = *reinterpret_cast<const float4*>(B + (size_t)(k0 + k) * NCOLS + gn);
            uint4 u;
            u.x = f2tf32(v.x); u.y = f2tf32(v.y);
            u.z = f2tf32(v.z); u.w = f2tf32(v.w);
            *reinterpret_cast<uint4*>(&Bs[k][b_n]) = u;
        }
        __syncthreads();

#pragma unroll
        for (int ks = 0; ks < 4; ks++) {
            const int kk = ks * 8;
            uint32_t a[2][4];
#pragma unroll
            for (int mi = 0; mi < 2; mi++) {
                int m0 = wm + mi * 16 + g;
                a[mi][0] = As[m0][kk + t];
                a[mi][1] = As[m0 + 8][kk + t];
                a[mi][2] = As[m0][kk + t + 4];
                a[mi][3] = As[m0 + 8][kk + t + 4];
            }
#pragma unroll
            for (int ni = 0; ni < 8; ni++) {
                int n0 = wn + ni * 8 + g;
                uint32_t b0 = Bs[kk + t][n0];
                uint32_t b1 = Bs[kk + t + 4][n0];
                mma_tf32(acc[0][ni], a[0][0], a[0][1], a[0][2], a[0][3], b0, b1);
                mma_tf32(acc[1][ni], a[1][0], a[1][1], a[1][2], a[1][3], b0, b1);
            }
        }
        __syncthreads();
    }

#pragma unroll
    for (int mi = 0; mi < 2; mi++) {
        int row0 = br * BM + wm + mi * 16 + g;
        int row1 = row0 + 8;
#pragma unroll
        for (int ni = 0; ni < 8; ni++) {
            int col = bc * BN + wn + ni * 8 + 2 * t;
            if (col < NCOLS) {
                if (row0 < M) {
                    float2 v = make_float2(acc[mi][ni][0], acc[mi][ni][1]);
                    *reinterpret_cast<float2*>(C + (size_t)row0 * NCOLS + col) = v;
                }
                if (row1 < M) {
                    float2 v = make_float2(acc[mi][ni][2], acc[mi][ni][3]);
                    *reinterpret_cast<float2*>(C + (size_t)row1 * NCOLS + col) = v;
                }
            }
        }
    }
}

// ---------------- per-node attention dots, layer 1 ----------------
__global__ void al1_kernel(const float* __restrict__ att_src,
                           const float* __restrict__ att_dst) {
    int idx = blockIdx.x * blockDim.x + threadIdx.x;
    if (idx >= NN * HEADS) return;
    int n = idx >> 3;
    int h = idx & 7;
    const float* row = g_h1 + (size_t)n * D1 + h * HID;
    const float* as = att_src + h * HID;
    const float* ad = att_dst + h * HID;
    float s = 0.f, d = 0.f;
#pragma unroll
    for (int c = 0; c < HID; c++) {
        float v = row[c];
        s += v * as[c];
        d += v * ad[c];
    }
    g_al_src[idx] = s;
    g_al_dst[idx] = d;
}

// ================= CSR build =================
__global__ void zero_deg_kernel() {
    int i = blockIdx.x * blockDim.x + threadIdx.x;
    if (i < NN) g_deg[i] = 0;
}

__global__ void hist_kernel(const int* __restrict__ ei) {
    int e = blockIdx.x * blockDim.x + threadIdx.x;
    if (e >= ETOT) return;
    int dst = (e < EE) ? ei[EE + e] : e - EE;
    atomicAdd(&g_deg[dst], 1);
}

__global__ void scan1_kernel() {
    __shared__ int s[256];
    int i = blockIdx.x * 256 + threadIdx.x;
    int v = (i < NN) ? g_deg[i] : 0;
    s[threadIdx.x] = v;
    __syncthreads();
#pragma unroll
    for (int d = 1; d < 256; d <<= 1) {
        int t = (threadIdx.x >= d) ? s[threadIdx.x - d] : 0;
        __syncthreads();
        s[threadIdx.x] += t;
        __syncthreads();
    }
    if (i < NN) g_off[i] = s[threadIdx.x] - v;   // exclusive
    if (threadIdx.x == 255) g_bsum[blockIdx.x] = s[255];
}

__global__ void scan2_kernel() {
    __shared__ int s[256];
    int v = (threadIdx.x < NB_SCAN) ? g_bsum[threadIdx.x] : 0;
    s[threadIdx.x] = v;
    __syncthreads();
#pragma unroll
    for (int d = 1; d < 256; d <<= 1) {
        int t = (threadIdx.x >= d) ? s[threadIdx.x - d] : 0;
        __syncthreads();
        s[threadIdx.x] += t;
        __syncthreads();
    }
    if (threadIdx.x < NB_SCAN) g_bsumx[threadIdx.x] = s[threadIdx.x] - v;
}

__global__ void scan3_kernel() {
    int i = blockIdx.x * 256 + threadIdx.x;
    if (i < NN) {
        int o = g_off[i] + g_bsumx[blockIdx.x];
        g_off[i] = o;
        g_wpos[i] = o;
    }
}

__global__ void scatter_kernel(const int* __restrict__ ei) {
    int e = blockIdx.x * blockDim.x + threadIdx.x;
    if (e >= ETOT) return;
    int src, dst;
    if (e < EE) { src = ei[e]; dst = ei[EE + e]; }
    else        { src = dst = e - EE; }
    int pos = atomicAdd(&g_wpos[dst], 1);
    g_esrc[pos] = src;
}

// ================= fused softmax + aggregation, layer 1 =================
// One warp per dst node. Lane owns 8 consecutive channels (head = lane>>2).
__global__ __launch_bounds__(256)
void fused_agg1(const float* __restrict__ b1) {
    int dst = (blockIdx.x * 256 + threadIdx.x) >> 5;
    int lane = threadIdx.x & 31;
    if (dst >= NN) return;
    int head = lane >> 2;
    float ald = g_al_dst[(size_t)dst * 8 + head];
    int start = g_off[dst];
    int deg = g_deg[dst];

    float acc[8];
#pragma unroll
    for (int j = 0; j < 8; j++) acc[j] = 0.0f;
    float denom = 0.0f;

#pragma unroll 2
    for (int j = 0; j < deg; j++) {
        int src = g_esrc[start + j];
        float p = __expf(leaky(g_al_src[(size_t)src * 8 + head] + ald));
        denom += p;
        const float4* hp = reinterpret_cast<const float4*>(
            g_h1 + (size_t)src * D1 + lane * 8);
        float4 a = hp[0];
        float4 b = hp[1];
        acc[0] += p * a.x; acc[1] += p * a.y;
        acc[2] += p * a.z; acc[3] += p * a.w;
        acc[4] += p * b.x; acc[5] += p * b.y;
        acc[6] += p * b.z; acc[7] += p * b.w;
    }

    float inv = 1.0f / (denom + 1e-16f);
    float o[8];
#pragma unroll
    for (int j = 0; j < 8; j++) {
        float v = acc[j] * inv + b1[lane * 8 + j];
        o[j] = v > 0.0f ? v : expm1f(v);       // fused ELU
    }
    float4* op = reinterpret_cast<float4*>(g_out1 + (size_t)dst * D1 + lane * 8);
    op[0] = make_float4(o[0], o[1], o[2], o[3]);
    op[1] = make_float4(o[4], o[5], o[6], o[7]);
}

// ---------------- per-node attention dots, layer 2 ----------------
__global__ void al2_kernel(const float* __restrict__ att_src2,
                           const float* __restrict__ att_dst2) {
    int n = blockIdx.x * blockDim.x + threadIdx.x;
    if (n >= NN) return;
    const float* row = g_h2 + (size_t)n * NCLS;
    float s = 0.f, d = 0.f;
#pragma unroll
    for (int j = 0; j < NCLS; j++) {
        float v = row[j];
        s += v * att_src2[j];
        d += v * att_dst2[j];
    }
    g_al2s[n] = s;
    g_al2d[n] = d;
}

// ================= fused softmax + aggregation, layer 2 =================
// One warp per dst. Lane owns channel `lane`; lanes 0..7 also own `lane+32`.
__global__ __launch_bounds__(256)
void fused_agg2(const float* __restrict__ b2, float* __restrict__ out) {
    int dst = (blockIdx.x * 256 + threadIdx.x) >> 5;
    int lane = threadIdx.x & 31;
    if (dst >= NN) return;
    float ald = g_al2d[dst];
    int start = g_off[dst];
    int deg = g_deg[dst];

    float acc0 = 0.0f, acc1 = 0.0f, denom = 0.0f;
#pragma unroll 2
    for (int j = 0; j < deg; j++) {
        int src = g_esrc[start + j];
        float p = __expf(leaky(g_al2s[src] + ald));
        denom += p;
        const float* row = g_h2 + (size_t)src * NCLS;
        acc0 += p * row[lane];
        if (lane < 8) acc1 += p * row[32 + lane];
    }
    float inv = 1.0f / (denom + 1e-16f);
    out[(size_t)dst * NCLS + lane] = acc0 * inv + b2[lane];
    if (lane < 8)
        out[(size_t)dst * NCLS + 32 + lane] = acc1 * inv + b2[32 + lane];
}

// ---------------- launch ----------------
extern "C" void kernel_launch(void* const* d_in, const int* in_sizes, int n_in,
                              void* d_out, int out_size) {
    const float* x        = (const float*)d_in[0];
    const int*   ei       = (const int*)  d_in[1];
    const float* W1       = (const float*)d_in[2];
    const float* att_src1 = (const float*)d_in[3];
    const float* att_dst1 = (const float*)d_in[4];
    const float* b1       = (const float*)d_in[5];
    const float* W2       = (const float*)d_in[6];
    const float* att_src2 = (const float*)d_in[7];
    const float* att_dst2 = (const float*)d_in[8];
    const float* b2       = (const float*)d_in[9];
    float* out = (float*)d_out;

    float *p_h1, *p_h2, *p_out1;
    cudaGetSymbolAddress((void**)&p_h1,   g_h1);
    cudaGetSymbolAddress((void**)&p_h2,   g_h2);
    cudaGetSymbolAddress((void**)&p_out1, g_out1);

    // ---- CSR build (independent of GEMM1; issue first for overlap-free order) ----
    zero_deg_kernel<<<NB_SCAN, 256>>>();
    hist_kernel<<<(ETOT + 255) / 256, 256>>>(ei);
    scan1_kernel<<<NB_SCAN, 256>>>();
    scan2_kernel<<<1, 256>>>();
    scan3_kernel<<<NB_SCAN, 256>>>();
    scatter_kernel<<<(ETOT + 255) / 256, 256>>>(ei);

    // 1. GEMM1 (tf32): h1 = x @ W1  [50000,512]x[512,256]
    {
        dim3 grid(D1 / 128, (NN + 127) / 128);
        tf32_gemm<128, 128, 4, D1, IN_CH><<<grid, 256>>>(x, W1, p_h1, NN);
    }

    // 2. attention dots layer 1
    al1_kernel<<<(NN * HEADS + 255) / 256, 256>>>(att_src1, att_dst1);

    // 3. fused softmax + aggregation + bias + ELU (layer 1)
    fused_agg1<<<(NN * 32 + 255) / 256, 256>>>(b1);

    // 4. GEMM2 (tf32): h2 = out1 @ W2  [50000,256]x[256,40]
    {
        dim3 grid(1, (NN + 255) / 256);
        tf32_gemm<256, 64, 8, NCLS, D1><<<grid, 256>>>(p_out1, W2, p_h2, NN);
    }

    // 5. attention dots layer 2
    al2_kernel<<<(NN + 255) / 256, 256>>>(att_src2, att_dst2);

    // 6. fused softmax + aggregation + bias (layer 2) -> d_out
    fused_agg2<<<(NN * 32 + 255) / 256, 256>>>(b2, out);
}

// round 4
// speedup vs baseline: 3.3911x; 1.2204x over previous
#include <cuda_runtime.h>
#include <cuda_bf16.h>
#include <math.h>
#include <stdint.h>

// Problem constants (fixed-shape problem)
#define NN      50000
#define EE      800000
#define ETOT    (EE + NN)      // self-loops appended
#define IN_CH   512
#define HID     32
#define HEADS   8
#define D1      (HID * HEADS)  // 256
#define NCLS    40
#define NEG_SLOPE 0.2f
#define NB_SCAN ((NN + 255) / 256)   // 196

// ---------------- scratch (device globals, no allocs allowed) ----------------
__device__ __align__(128) float g_h1[NN * D1];       // 51.2 MB
__device__ __align__(128) float g_out1[NN * D1];     // 51.2 MB (post-ELU)
__device__ __align__(128) float g_al_src[NN * HEADS];
__device__ __align__(128) float g_al_dst[NN * HEADS];
__device__ __align__(128) float g_h2[NN * NCLS];     // 8 MB
__device__ __align__(128) float g_al2s[NN];
__device__ __align__(128) float g_al2d[NN];
// CSR-by-dst
__device__ int g_deg[NN];
__device__ int g_off[NN];
__device__ int g_wpos[NN];
__device__ int g_esrc[ETOT];
__device__ int g_bsum[NB_SCAN];
__device__ int g_bsumx[NB_SCAN];

// ---------------- helpers ----------------
__device__ __forceinline__ float leaky(float x) {
    return x > 0.0f ? x : NEG_SLOPE * x;
}

__device__ __forceinline__ uint32_t f2tf32(float f) {
    uint32_t r;
    asm("cvt.rn.tf32.f32 %0, %1;" : "=r"(r) : "f"(f));
    return r;
}

__device__ __forceinline__ void mma_tf32(float c[4], uint32_t a0, uint32_t a1,
                                         uint32_t a2, uint32_t a3,
                                         uint32_t b0, uint32_t b1) {
    asm volatile(
        "mma.sync.aligned.m16n8k8.row.col.f32.tf32.tf32.f32 "
        "{%0,%1,%2,%3}, {%4,%5,%6,%7}, {%8,%9}, {%0,%1,%2,%3};\n"
        : "+f"(c[0]), "+f"(c[1]), "+f"(c[2]), "+f"(c[3])
        : "r"(a0), "r"(a1), "r"(a2), "r"(a3), "r"(b0), "r"(b1));
}

// =====================================================================
// tf32 tensor-core GEMM with register double-buffering.
// C[M,N] = A[M,K] @ B[K,N], row-major. 256 threads, warp tile 32x64.
// FUSE_AL: additionally compute als[row] = C_row . as2, ald[row] = C_row . ad2
//          (requires BN >= NCOLS so each row's cols live in one warp).
// =====================================================================
template <int BM, int BN, int WARPS_M, int NCOLS, int KTOT, bool FUSE_AL>
__global__ __launch_bounds__(256)
void tf32_gemm(const float* __restrict__ A, const float* __restrict__ B,
               float* __restrict__ C, int M,
               const float* __restrict__ as2, const float* __restrict__ ad2,
               float* __restrict__ als, float* __restrict__ ald) {
    constexpr int APAD = 36;
    constexpr int BPAD = BN + 8;
    __shared__ uint32_t As[BM][APAD];
    __shared__ uint32_t Bs[32][BPAD];

    const int tid = threadIdx.x;
    const int lane = tid & 31;
    const int warpId = tid >> 5;
    const int br = blockIdx.y;
    const int bc = blockIdx.x;

    const int wm = (warpId % WARPS_M) * 32;
    const int wn = (warpId / WARPS_M) * 64;
    const int g = lane >> 2;
    const int t = lane & 3;

    float acc[2][8][4];
#pragma unroll
    for (int mi = 0; mi < 2; mi++)
#pragma unroll
        for (int ni = 0; ni < 8; ni++)
#pragma unroll
            for (int r = 0; r < 4; r++) acc[mi][ni][r] = 0.0f;

    const int a_m = tid >> 3;
    const int a_k = (tid & 7) * 4;
    constexpr int AREG = BM / 32;
    constexpr int TPR = BN / 4;
    constexpr int BROWS = 256 / TPR;
    constexpr int BITER = 32 / BROWS;
    const int b_n = (tid % TPR) * 4;
    const int b_k = tid / TPR;

    float4 ra[AREG];
    float4 rb[BITER];

    // prologue: load chunk 0 into registers
#pragma unroll
    for (int r = 0; r < AREG; r++) {
        int grow = br * BM + r * 32 + a_m;
        ra[r] = make_float4(0.f, 0.f, 0.f, 0.f);
        if (grow < M)
            ra[r] = *reinterpret_cast<const float4*>(A + (size_t)grow * KTOT + a_k);
    }
#pragma unroll
    for (int r = 0; r < BITER; r++) {
        int gn = bc * BN + b_n;
        rb[r] = make_float4(0.f, 0.f, 0.f, 0.f);
        if (gn < NCOLS)
            rb[r] = *reinterpret_cast<const float4*>(B + (size_t)(r * BROWS + b_k) * NCOLS + gn);
    }

    for (int k0 = 0; k0 < KTOT; k0 += 32) {
        // ---- store staged registers to smem (RN tf32 convert) ----
#pragma unroll
        for (int r = 0; r < AREG; r++) {
            uint4 u;
            u.x = f2tf32(ra[r].x); u.y = f2tf32(ra[r].y);
            u.z = f2tf32(ra[r].z); u.w = f2tf32(ra[r].w);
            *reinterpret_cast<uint4*>(&As[r * 32 + a_m][a_k]) = u;
        }
#pragma unroll
        for (int r = 0; r < BITER; r++) {
            uint4 u;
            u.x = f2tf32(rb[r].x); u.y = f2tf32(rb[r].y);
            u.z = f2tf32(rb[r].z); u.w = f2tf32(rb[r].w);
            *reinterpret_cast<uint4*>(&Bs[r * BROWS + b_k][b_n]) = u;
        }
        __syncthreads();

        // ---- prefetch next chunk into registers (overlaps compute) ----
        if (k0 + 32 < KTOT) {
#pragma unroll
            for (int r = 0; r < AREG; r++) {
                int grow = br * BM + r * 32 + a_m;
                ra[r] = make_float4(0.f, 0.f, 0.f, 0.f);
                if (grow < M)
                    ra[r] = *reinterpret_cast<const float4*>(
                        A + (size_t)grow * KTOT + k0 + 32 + a_k);
            }
#pragma unroll
            for (int r = 0; r < BITER; r++) {
                int gn = bc * BN + b_n;
                rb[r] = make_float4(0.f, 0.f, 0.f, 0.f);
                if (gn < NCOLS)
                    rb[r] = *reinterpret_cast<const float4*>(
                        B + (size_t)(k0 + 32 + r * BROWS + b_k) * NCOLS + gn);
            }
        }

        // ---- compute: 4 k-steps of 8 ----
#pragma unroll
        for (int ks = 0; ks < 4; ks++) {
            const int kk = ks * 8;
            uint32_t a[2][4];
#pragma unroll
            for (int mi = 0; mi < 2; mi++) {
                int m0 = wm + mi * 16 + g;
                a[mi][0] = As[m0][kk + t];
                a[mi][1] = As[m0 + 8][kk + t];
                a[mi][2] = As[m0][kk + t + 4];
                a[mi][3] = As[m0 + 8][kk + t + 4];
            }
#pragma unroll
            for (int ni = 0; ni < 8; ni++) {
                int n0 = wn + ni * 8 + g;
                uint32_t b0 = Bs[kk + t][n0];
                uint32_t b1 = Bs[kk + t + 4][n0];
                mma_tf32(acc[0][ni], a[0][0], a[0][1], a[0][2], a[0][3], b0, b1);
                mma_tf32(acc[1][ni], a[1][0], a[1][1], a[1][2], a[1][3], b0, b1);
            }
        }
        __syncthreads();
    }

    // ---- epilogue: store C ----
#pragma unroll
    for (int mi = 0; mi < 2; mi++) {
        int row0 = br * BM + wm + mi * 16 + g;
        int row1 = row0 + 8;
#pragma unroll
        for (int ni = 0; ni < 8; ni++) {
            int col = bc * BN + wn + ni * 8 + 2 * t;
            if (col < NCOLS) {
                if (row0 < M) {
                    float2 v = make_float2(acc[mi][ni][0], acc[mi][ni][1]);
                    *reinterpret_cast<float2*>(C + (size_t)row0 * NCOLS + col) = v;
                }
                if (row1 < M) {
                    float2 v = make_float2(acc[mi][ni][2], acc[mi][ni][3]);
                    *reinterpret_cast<float2*>(C + (size_t)row1 * NCOLS + col) = v;
                }
            }
        }
    }

    // ---- fused attention dots (layer 2): reduce within warp, no atomics ----
    if (FUSE_AL) {
#pragma unroll
        for (int mi = 0; mi < 2; mi++) {
            float ps0 = 0.f, ps1 = 0.f, pd0 = 0.f, pd1 = 0.f;
#pragma unroll
            for (int ni = 0; ni < 8; ni++) {
                int col = wn + ni * 8 + 2 * t;
                if (col < NCOLS) {
                    float a0 = as2[col], a1 = as2[col + 1];
                    float d0 = ad2[col], d1 = ad2[col + 1];
                    ps0 += acc[mi][ni][0] * a0 + acc[mi][ni][1] * a1;
                    ps1 += acc[mi][ni][2] * a0 + acc[mi][ni][3] * a1;
                    pd0 += acc[mi][ni][0] * d0 + acc[mi][ni][1] * d1;
                    pd1 += acc[mi][ni][2] * d0 + acc[mi][ni][3] * d1;
                }
            }
            // reduce across the 4 t-lanes (same g -> same rows)
#pragma unroll
            for (int off = 1; off < 4; off <<= 1) {
                ps0 += __shfl_xor_sync(0xffffffffu, ps0, off);
                ps1 += __shfl_xor_sync(0xffffffffu, ps1, off);
                pd0 += __shfl_xor_sync(0xffffffffu, pd0, off);
                pd1 += __shfl_xor_sync(0xffffffffu, pd1, off);
            }
            if (t == 0) {
                int row0 = br * BM + wm + mi * 16 + g;
                int row1 = row0 + 8;
                if (row0 < M) { als[row0] = ps0; ald[row0] = pd0; }
                if (row1 < M) { als[row1] = ps1; ald[row1] = pd1; }
            }
        }
    }
}

// ---------------- per-node attention dots, layer 1 ----------------
__global__ void al1_kernel(const float* __restrict__ att_src,
                           const float* __restrict__ att_dst) {
    int idx = blockIdx.x * blockDim.x + threadIdx.x;
    if (idx >= NN * HEADS) return;
    int n = idx >> 3;
    int h = idx & 7;
    const float* row = g_h1 + (size_t)n * D1 + h * HID;
    const float* as = att_src + h * HID;
    const float* ad = att_dst + h * HID;
    float s = 0.f, d = 0.f;
#pragma unroll
    for (int c = 0; c < HID; c++) {
        float v = row[c];
        s += v * as[c];
        d += v * ad[c];
    }
    g_al_src[idx] = s;
    g_al_dst[idx] = d;
}

// ================= CSR build =================
__global__ void zero_deg_kernel() {
    int i = blockIdx.x * blockDim.x + threadIdx.x;
    if (i < NN) g_deg[i] = 0;
}

__global__ void hist_kernel(const int* __restrict__ ei) {
    int e = blockIdx.x * blockDim.x + threadIdx.x;
    if (e >= ETOT) return;
    int dst = (e < EE) ? ei[EE + e] : e - EE;
    atomicAdd(&g_deg[dst], 1);
}

__global__ void scan1_kernel() {
    __shared__ int s[256];
    int i = blockIdx.x * 256 + threadIdx.x;
    int v = (i < NN) ? g_deg[i] : 0;
    s[threadIdx.x] = v;
    __syncthreads();
#pragma unroll
    for (int d = 1; d < 256; d <<= 1) {
        int t = (threadIdx.x >= d) ? s[threadIdx.x - d] : 0;
        __syncthreads();
        s[threadIdx.x] += t;
        __syncthreads();
    }
    if (i < NN) g_off[i] = s[threadIdx.x] - v;   // exclusive
    if (threadIdx.x == 255) g_bsum[blockIdx.x] = s[255];
}

__global__ void scan2_kernel() {
    __shared__ int s[256];
    int v = (threadIdx.x < NB_SCAN) ? g_bsum[threadIdx.x] : 0;
    s[threadIdx.x] = v;
    __syncthreads();
#pragma unroll
    for (int d = 1; d < 256; d <<= 1) {
        int t = (threadIdx.x >= d) ? s[threadIdx.x - d] : 0;
        __syncthreads();
        s[threadIdx.x] += t;
        __syncthreads();
    }
    if (threadIdx.x < NB_SCAN) g_bsumx[threadIdx.x] = s[threadIdx.x] - v;
}

__global__ void scan3_kernel() {
    int i = blockIdx.x * 256 + threadIdx.x;
    if (i < NN) {
        int o = g_off[i] + g_bsumx[blockIdx.x];
        g_off[i] = o;
        g_wpos[i] = o;
    }
}

__global__ void scatter_kernel(const int* __restrict__ ei) {
    int e = blockIdx.x * blockDim.x + threadIdx.x;
    if (e >= ETOT) return;
    int src, dst;
    if (e < EE) { src = ei[e]; dst = ei[EE + e]; }
    else        { src = dst = e - EE; }
    int pos = atomicAdd(&g_wpos[dst], 1);
    g_esrc[pos] = src;
}

// ================= fused softmax + aggregation, layer 1 =================
// One warp per dst. Lane owns 8 consecutive channels (head = lane>>2).
// Edge ids staged 32 at a time via coalesced load + shfl broadcast.
__global__ __launch_bounds__(256)
void fused_agg1(const float* __restrict__ b1) {
    int dst = (blockIdx.x * 256 + threadIdx.x) >> 5;
    int lane = threadIdx.x & 31;
    if (dst >= NN) return;
    int head = lane >> 2;
    float ald = g_al_dst[(size_t)dst * 8 + head];
    int start = g_off[dst];
    int deg = g_deg[dst];

    float acc[8];
#pragma unroll
    for (int j = 0; j < 8; j++) acc[j] = 0.0f;
    float denom = 0.0f;

    for (int base = 0; base < deg; base += 32) {
        int n = min(32, deg - base);
        int r_src = (lane < n) ? g_esrc[start + base + lane] : 0;
        for (int j = 0; j < n; j++) {
            int src = __shfl_sync(0xffffffffu, r_src, j);
            float p = __expf(leaky(g_al_src[(size_t)src * 8 + head] + ald));
            denom += p;
            const float4* hp = reinterpret_cast<const float4*>(
                g_h1 + (size_t)src * D1 + lane * 8);
            float4 a = hp[0];
            float4 b = hp[1];
            acc[0] += p * a.x; acc[1] += p * a.y;
            acc[2] += p * a.z; acc[3] += p * a.w;
            acc[4] += p * b.x; acc[5] += p * b.y;
            acc[6] += p * b.z; acc[7] += p * b.w;
        }
    }

    float inv = 1.0f / (denom + 1e-16f);
    float o[8];
#pragma unroll
    for (int j = 0; j < 8; j++) {
        float v = acc[j] * inv + b1[lane * 8 + j];
        o[j] = v > 0.0f ? v : expm1f(v);       // fused ELU
    }
    float4* op = reinterpret_cast<float4*>(g_out1 + (size_t)dst * D1 + lane * 8);
    op[0] = make_float4(o[0], o[1], o[2], o[3]);
    op[1] = make_float4(o[4], o[5], o[6], o[7]);
}

// ================= fused softmax + aggregation, layer 2 =================
// One warp per dst. Edge ids AND al2s values staged per lane, shfl broadcast.
__global__ __launch_bounds__(256)
void fused_agg2(const float* __restrict__ b2, float* __restrict__ out) {
    int dst = (blockIdx.x * 256 + threadIdx.x) >> 5;
    int lane = threadIdx.x & 31;
    if (dst >= NN) return;
    float ald = g_al2d[dst];
    int start = g_off[dst];
    int deg = g_deg[dst];

    float acc0 = 0.0f, acc1 = 0.0f, denom = 0.0f;
    for (int base = 0; base < deg; base += 32) {
        int n = min(32, deg - base);
        int r_src = 0;
        float r_al = 0.0f;
        if (lane < n) {
            r_src = g_esrc[start + base + lane];
            r_al = g_al2s[r_src];
        }
        for (int j = 0; j < n; j++) {
            int src = __shfl_sync(0xffffffffu, r_src, j);
            float alv = __shfl_sync(0xffffffffu, r_al, j);
            float p = __expf(leaky(alv + ald));
            denom += p;
            const float* row = g_h2 + (size_t)src * NCLS;
            acc0 += p * row[lane];
            if (lane < 8) acc1 += p * row[32 + lane];
        }
    }
    float inv = 1.0f / (denom + 1e-16f);
    out[(size_t)dst * NCLS + lane] = acc0 * inv + b2[lane];
    if (lane < 8)
        out[(size_t)dst * NCLS + 32 + lane] = acc1 * inv + b2[32 + lane];
}

// ---------------- launch ----------------
extern "C" void kernel_launch(void* const* d_in, const int* in_sizes, int n_in,
                              void* d_out, int out_size) {
    const float* x        = (const float*)d_in[0];
    const int*   ei       = (const int*)  d_in[1];
    const float* W1       = (const float*)d_in[2];
    const float* att_src1 = (const float*)d_in[3];
    const float* att_dst1 = (const float*)d_in[4];
    const float* b1       = (const float*)d_in[5];
    const float* W2       = (const float*)d_in[6];
    const float* att_src2 = (const float*)d_in[7];
    const float* att_dst2 = (const float*)d_in[8];
    const float* b2       = (const float*)d_in[9];
    float* out = (float*)d_out;

    float *p_h1, *p_h2, *p_out1, *p_al2s, *p_al2d;
    cudaGetSymbolAddress((void**)&p_h1,   g_h1);
    cudaGetSymbolAddress((void**)&p_h2,   g_h2);
    cudaGetSymbolAddress((void**)&p_out1, g_out1);
    cudaGetSymbolAddress((void**)&p_al2s, g_al2s);
    cudaGetSymbolAddress((void**)&p_al2d, g_al2d);

    // ---- CSR build ----
    zero_deg_kernel<<<NB_SCAN, 256>>>();
    hist_kernel<<<(ETOT + 255) / 256, 256>>>(ei);
    scan1_kernel<<<NB_SCAN, 256>>>();
    scan2_kernel<<<1, 256>>>();
    scan3_kernel<<<NB_SCAN, 256>>>();
    scatter_kernel<<<(ETOT + 255) / 256, 256>>>(ei);

    // 1. GEMM1 (tf32, double-buffered): h1 = x @ W1  [50000,512]x[512,256]
    {
        dim3 grid(D1 / 128, (NN + 127) / 128);
        tf32_gemm<128, 128, 4, D1, IN_CH, false><<<grid, 256>>>(
            x, W1, p_h1, NN, nullptr, nullptr, nullptr, nullptr);
    }

    // 2. attention dots layer 1
    al1_kernel<<<(NN * HEADS + 255) / 256, 256>>>(att_src1, att_dst1);

    // 3. fused softmax + aggregation + bias + ELU (layer 1)
    fused_agg1<<<(NN * 32 + 255) / 256, 256>>>(b1);

    // 4. GEMM2 (tf32, double-buffered) + fused al2 dots:
    //    h2 = out1 @ W2  [50000,256]x[256,40]; al2s/al2d from epilogue
    {
        dim3 grid(1, (NN + 255) / 256);
        tf32_gemm<256, 64, 8, NCLS, D1, true><<<grid, 256>>>(
            p_out1, W2, p_h2, NN, att_src2, att_dst2, p_al2s, p_al2d);
    }

    // 5. fused softmax + aggregation + bias (layer 2) -> d_out
    fused_agg2<<<(NN * 32 + 255) / 256, 256>>>(b2, out);
}

// round 6
// speedup vs baseline: 3.8075x; 1.1228x over previous
#include <cuda_runtime.h>
#include <cuda_fp16.h>
#include <math.h>
#include <stdint.h>

// Problem constants (fixed-shape problem)
#define NN      50000
#define EE      800000
#define ETOT    (EE + NN)      // self-loops appended
#define IN_CH   512
#define HID     32
#define HEADS   8
#define D1      (HID * HEADS)  // 256
#define NCLS    40
#define NEG_SLOPE 0.2f
#define NB_SCAN ((NN + 255) / 256)   // 196

// ---------------- scratch (device globals, no allocs allowed) ----------------
__device__ __align__(128) __half g_h1h[NN * D1];         // 25.6 MB (fp16 h1)
__device__ __align__(128) float g_out1[NN * D1];         // 51.2 MB (post-ELU)
__device__ __align__(128) float g_al_src[NN * HEADS];
__device__ __align__(128) float g_al_dst[NN * HEADS];
__device__ __align__(128) float g_h2[NN * NCLS];         // 8 MB
__device__ __align__(128) float g_al2s[NN];
__device__ __align__(128) float g_al2d[NN];
// CSR-by-dst
__device__ int g_deg[NN];
__device__ int g_off[NN];
__device__ int g_wpos[NN];
__device__ int g_esrc[ETOT];
__device__ int g_bsum[NB_SCAN];
__device__ int g_bsumx[NB_SCAN];

// ---------------- helpers ----------------
__device__ __forceinline__ float leaky(float x) {
    return x > 0.0f ? x : NEG_SLOPE * x;
}

__device__ __forceinline__ uint32_t f2tf32(float f) {
    uint32_t r;
    asm("cvt.rn.tf32.f32 %0, %1;" : "=r"(r) : "f"(f));
    return r;
}

__device__ __forceinline__ void mma_tf32(float c[4], uint32_t a0, uint32_t a1,
                                         uint32_t a2, uint32_t a3,
                                         uint32_t b0, uint32_t b1) {
    asm volatile(
        "mma.sync.aligned.m16n8k8.row.col.f32.tf32.tf32.f32 "
        "{%0,%1,%2,%3}, {%4,%5,%6,%7}, {%8,%9}, {%0,%1,%2,%3};\n"
        : "+f"(c[0]), "+f"(c[1]), "+f"(c[2]), "+f"(c[3])
        : "r"(a0), "r"(a1), "r"(a2), "r"(a3), "r"(b0), "r"(b1));
}

// =====================================================================
// tf32 tensor-core GEMM with register double-buffering.
// C[M,N] = A[M,K] @ B[K,N], row-major. 256 threads, warp tile 32x64.
// OUT_FP16: store C as fp16. FUSE_AL: also write per-row attention dots.
// =====================================================================
template <int BM, int BN, int WARPS_M, int NCOLS, int KTOT, bool FUSE_AL, bool OUT_FP16>
__global__ __launch_bounds__(256)
void tf32_gemm(const float* __restrict__ A, const float* __restrict__ B,
               float* __restrict__ Cf, __half* __restrict__ Ch, int M,
               const float* __restrict__ as2, const float* __restrict__ ad2,
               float* __restrict__ als, float* __restrict__ ald) {
    constexpr int APAD = 36;
    constexpr int BPAD = BN + 8;
    __shared__ uint32_t As[BM][APAD];
    __shared__ uint32_t Bs[32][BPAD];

    const int tid = threadIdx.x;
    const int lane = tid & 31;
    const int warpId = tid >> 5;
    const int br = blockIdx.y;
    const int bc = blockIdx.x;

    const int wm = (warpId % WARPS_M) * 32;
    const int wn = (warpId / WARPS_M) * 64;
    const int g = lane >> 2;
    const int t = lane & 3;

    float acc[2][8][4];
#pragma unroll
    for (int mi = 0; mi < 2; mi++)
#pragma unroll
        for (int ni = 0; ni < 8; ni++)
#pragma unroll
            for (int r = 0; r < 4; r++) acc[mi][ni][r] = 0.0f;

    const int a_m = tid >> 3;
    const int a_k = (tid & 7) * 4;
    constexpr int AREG = BM / 32;
    constexpr int TPR = BN / 4;
    constexpr int BROWS = 256 / TPR;
    constexpr int BITER = 32 / BROWS;
    const int b_n = (tid % TPR) * 4;
    const int b_k = tid / TPR;

    float4 ra[AREG];
    float4 rb[BITER];

    // prologue: load chunk 0 into registers
#pragma unroll
    for (int r = 0; r < AREG; r++) {
        int grow = br * BM + r * 32 + a_m;
        ra[r] = make_float4(0.f, 0.f, 0.f, 0.f);
        if (grow < M)
            ra[r] = *reinterpret_cast<const float4*>(A + (size_t)grow * KTOT + a_k);
    }
#pragma unroll
    for (int r = 0; r < BITER; r++) {
        int gn = bc * BN + b_n;
        rb[r] = make_float4(0.f, 0.f, 0.f, 0.f);
        if (gn < NCOLS)
            rb[r] = *reinterpret_cast<const float4*>(B + (size_t)(r * BROWS + b_k) * NCOLS + gn);
    }

    for (int k0 = 0; k0 < KTOT; k0 += 32) {
#pragma unroll
        for (int r = 0; r < AREG; r++) {
            uint4 u;
            u.x = f2tf32(ra[r].x); u.y = f2tf32(ra[r].y);
            u.z = f2tf32(ra[r].z); u.w = f2tf32(ra[r].w);
            *reinterpret_cast<uint4*>(&As[r * 32 + a_m][a_k]) = u;
        }
#pragma unroll
        for (int r = 0; r < BITER; r++) {
            uint4 u;
            u.x = f2tf32(rb[r].x); u.y = f2tf32(rb[r].y);
            u.z = f2tf32(rb[r].z); u.w = f2tf32(rb[r].w);
            *reinterpret_cast<uint4*>(&Bs[r * BROWS + b_k][b_n]) = u;
        }
        __syncthreads();

        if (k0 + 32 < KTOT) {
#pragma unroll
            for (int r = 0; r < AREG; r++) {
                int grow = br * BM + r * 32 + a_m;
                ra[r] = make_float4(0.f, 0.f, 0.f, 0.f);
                if (grow < M)
                    ra[r] = *reinterpret_cast<const float4*>(
                        A + (size_t)grow * KTOT + k0 + 32 + a_k);
            }
#pragma unroll
            for (int r = 0; r < BITER; r++) {
                int gn = bc * BN + b_n;
                rb[r] = make_float4(0.f, 0.f, 0.f, 0.f);
                if (gn < NCOLS)
                    rb[r] = *reinterpret_cast<const float4*>(
                        B + (size_t)(k0 + 32 + r * BROWS + b_k) * NCOLS + gn);
            }
        }

#pragma unroll
        for (int ks = 0; ks < 4; ks++) {
            const int kk = ks * 8;
            uint32_t a[2][4];
#pragma unroll
            for (int mi = 0; mi < 2; mi++) {
                int m0 = wm + mi * 16 + g;
                a[mi][0] = As[m0][kk + t];
                a[mi][1] = As[m0 + 8][kk + t];
                a[mi][2] = As[m0][kk + t + 4];
                a[mi][3] = As[m0 + 8][kk + t + 4];
            }
#pragma unroll
            for (int ni = 0; ni < 8; ni++) {
                int n0 = wn + ni * 8 + g;
                uint32_t b0 = Bs[kk + t][n0];
                uint32_t b1 = Bs[kk + t + 4][n0];
                mma_tf32(acc[0][ni], a[0][0], a[0][1], a[0][2], a[0][3], b0, b1);
                mma_tf32(acc[1][ni], a[1][0], a[1][1], a[1][2], a[1][3], b0, b1);
            }
        }
        __syncthreads();
    }

    // ---- epilogue: store C ----
#pragma unroll
    for (int mi = 0; mi < 2; mi++) {
        int row0 = br * BM + wm + mi * 16 + g;
        int row1 = row0 + 8;
#pragma unroll
        for (int ni = 0; ni < 8; ni++) {
            int col = bc * BN + wn + ni * 8 + 2 * t;
            if (col < NCOLS) {
                if (OUT_FP16) {
                    if (row0 < M)
                        *reinterpret_cast<__half2*>(Ch + (size_t)row0 * NCOLS + col) =
                            __float22half2_rn(make_float2(acc[mi][ni][0], acc[mi][ni][1]));
                    if (row1 < M)
                        *reinterpret_cast<__half2*>(Ch + (size_t)row1 * NCOLS + col) =
                            __float22half2_rn(make_float2(acc[mi][ni][2], acc[mi][ni][3]));
                } else {
                    if (row0 < M) {
                        float2 v = make_float2(acc[mi][ni][0], acc[mi][ni][1]);
                        *reinterpret_cast<float2*>(Cf + (size_t)row0 * NCOLS + col) = v;
                    }
                    if (row1 < M) {
                        float2 v = make_float2(acc[mi][ni][2], acc[mi][ni][3]);
                        *reinterpret_cast<float2*>(Cf + (size_t)row1 * NCOLS + col) = v;
                    }
                }
            }
        }
    }

    // ---- fused attention dots (layer 2) ----
    if (FUSE_AL) {
#pragma unroll
        for (int mi = 0; mi < 2; mi++) {
            float ps0 = 0.f, ps1 = 0.f, pd0 = 0.f, pd1 = 0.f;
#pragma unroll
            for (int ni = 0; ni < 8; ni++) {
                int col = wn + ni * 8 + 2 * t;
                if (col < NCOLS) {
                    float a0 = as2[col], a1 = as2[col + 1];
                    float d0 = ad2[col], d1 = ad2[col + 1];
                    ps0 += acc[mi][ni][0] * a0 + acc[mi][ni][1] * a1;
                    ps1 += acc[mi][ni][2] * a0 + acc[mi][ni][3] * a1;
                    pd0 += acc[mi][ni][0] * d0 + acc[mi][ni][1] * d1;
                    pd1 += acc[mi][ni][2] * d0 + acc[mi][ni][3] * d1;
                }
            }
#pragma unroll
            for (int off = 1; off < 4; off <<= 1) {
                ps0 += __shfl_xor_sync(0xffffffffu, ps0, off);
                ps1 += __shfl_xor_sync(0xffffffffu, ps1, off);
                pd0 += __shfl_xor_sync(0xffffffffu, pd0, off);
                pd1 += __shfl_xor_sync(0xffffffffu, pd1, off);
            }
            if (t == 0) {
                int row0 = br * BM + wm + mi * 16 + g;
                int row1 = row0 + 8;
                if (row0 < M) { als[row0] = ps0; ald[row0] = pd0; }
                if (row1 < M) { als[row1] = ps1; ald[row1] = pd1; }
            }
        }
    }
}

// ---------------- per-node attention dots, layer 1 (fp16 h1) ----------------
__global__ void al1_kernel(const float* __restrict__ att_src,
                           const float* __restrict__ att_dst) {
    int idx = blockIdx.x * blockDim.x + threadIdx.x;
    if (idx >= NN * HEADS) return;
    int n = idx >> 3;
    int h = idx & 7;
    const uint4* row = reinterpret_cast<const uint4*>(
        g_h1h + (size_t)n * D1 + h * HID);
    const float* as = att_src + h * HID;
    const float* ad = att_dst + h * HID;
    float s = 0.f, d = 0.f;
#pragma unroll
    for (int q = 0; q < 4; q++) {          // 4 x uint4 = 32 fp16
        uint4 u = row[q];
        uint32_t w[4] = {u.x, u.y, u.z, u.w};
#pragma unroll
        for (int r = 0; r < 4; r++) {
            float2 f = __half22float2(*reinterpret_cast<__half2*>(&w[r]));
            int c = q * 8 + r * 2;
            s += f.x * as[c] + f.y * as[c + 1];
            d += f.x * ad[c] + f.y * ad[c + 1];
        }
    }
    g_al_src[idx] = s;
    g_al_dst[idx] = d;
}

// ================= CSR build =================
__global__ void zero_deg_kernel() {
    int i = blockIdx.x * blockDim.x + threadIdx.x;
    if (i < NN) g_deg[i] = 0;
}

__global__ void hist_kernel(const int* __restrict__ ei) {
    int e = blockIdx.x * blockDim.x + threadIdx.x;
    if (e >= ETOT) return;
    int dst = (e < EE) ? ei[EE + e] : e - EE;
    atomicAdd(&g_deg[dst], 1);
}

__global__ void scan1_kernel() {
    __shared__ int s[256];
    int i = blockIdx.x * 256 + threadIdx.x;
    int v = (i < NN) ? g_deg[i] : 0;
    s[threadIdx.x] = v;
    __syncthreads();
#pragma unroll
    for (int d = 1; d < 256; d <<= 1) {
        int t = (threadIdx.x >= d) ? s[threadIdx.x - d] : 0;
        __syncthreads();
        s[threadIdx.x] += t;
        __syncthreads();
    }
    if (i < NN) g_off[i] = s[threadIdx.x] - v;   // exclusive
    if (threadIdx.x == 255) g_bsum[blockIdx.x] = s[255];
}

__global__ void scan2_kernel() {
    __shared__ int s[256];
    int v = (threadIdx.x < NB_SCAN) ? g_bsum[threadIdx.x] : 0;
    s[threadIdx.x] = v;
    __syncthreads();
#pragma unroll
    for (int d = 1; d < 256; d <<= 1) {
        int t = (threadIdx.x >= d) ? s[threadIdx.x - d] : 0;
        __syncthreads();
        s[threadIdx.x] += t;
        __syncthreads();
    }
    if (threadIdx.x < NB_SCAN) g_bsumx[threadIdx.x] = s[threadIdx.x] - v;
}

__global__ void scan3_kernel() {
    int i = blockIdx.x * 256 + threadIdx.x;
    if (i < NN) {
        int o = g_off[i] + g_bsumx[blockIdx.x];
        g_off[i] = o;
        g_wpos[i] = o;
    }
}

__global__ void scatter_kernel(const int* __restrict__ ei) {
    int e = blockIdx.x * blockDim.x + threadIdx.x;
    if (e >= ETOT) return;
    int src, dst;
    if (e < EE) { src = ei[e]; dst = ei[EE + e]; }
    else        { src = dst = e - EE; }
    int pos = atomicAdd(&g_wpos[dst], 1);
    g_esrc[pos] = src;
}

// ================= fused softmax + aggregation, layer 1 =================
// One warp per dst. Lane owns 8 consecutive channels (head = lane>>2).
// h1 gathered as fp16 (16B per lane per edge), accumulate fp32.
__global__ __launch_bounds__(256)
void fused_agg1(const float* __restrict__ b1) {
    int dst = (blockIdx.x * 256 + threadIdx.x) >> 5;
    int lane = threadIdx.x & 31;
    if (dst >= NN) return;
    int head = lane >> 2;
    float ald = g_al_dst[(size_t)dst * 8 + head];
    int start = g_off[dst];
    int deg = g_deg[dst];

    float acc[8];
#pragma unroll
    for (int j = 0; j < 8; j++) acc[j] = 0.0f;
    float denom = 0.0f;

    for (int base = 0; base < deg; base += 32) {
        int n = min(32, deg - base);
        int r_src = (lane < n) ? g_esrc[start + base + lane] : 0;
        for (int j = 0; j < n; j++) {
            int src = __shfl_sync(0xffffffffu, r_src, j);
            float p = __expf(leaky(g_al_src[(size_t)src * 8 + head] + ald));
            denom += p;
            uint4 u = *reinterpret_cast<const uint4*>(
                g_h1h + (size_t)src * D1 + lane * 8);
            float2 f0 = __half22float2(*reinterpret_cast<__half2*>(&u.x));
            float2 f1 = __half22float2(*reinterpret_cast<__half2*>(&u.y));
            float2 f2 = __half22float2(*reinterpret_cast<__half2*>(&u.z));
            float2 f3 = __half22float2(*reinterpret_cast<__half2*>(&u.w));
            acc[0] += p * f0.x; acc[1] += p * f0.y;
            acc[2] += p * f1.x; acc[3] += p * f1.y;
            acc[4] += p * f2.x; acc[5] += p * f2.y;
            acc[6] += p * f3.x; acc[7] += p * f3.y;
        }
    }

    float inv = 1.0f / (denom + 1e-16f);
    float o[8];
#pragma unroll
    for (int j = 0; j < 8; j++) {
        float v = acc[j] * inv + b1[lane * 8 + j];
        o[j] = v > 0.0f ? v : expm1f(v);       // fused ELU
    }
    float4* op = reinterpret_cast<float4*>(g_out1 + (size_t)dst * D1 + lane * 8);
    op[0] = make_float4(o[0], o[1], o[2], o[3]);
    op[1] = make_float4(o[4], o[5], o[6], o[7]);
}

// ================= fused softmax + aggregation, layer 2 =================
__global__ __launch_bounds__(256)
void fused_agg2(const float* __restrict__ b2, float* __restrict__ out) {
    int dst = (blockIdx.x * 256 + threadIdx.x) >> 5;
    int lane = threadIdx.x & 31;
    if (dst >= NN) return;
    float ald = g_al2d[dst];
    int start = g_off[dst];
    int deg = g_deg[dst];

    float acc0 = 0.0f, acc1 = 0.0f, denom = 0.0f;
    for (int base = 0; base < deg; base += 32) {
        int n = min(32, deg - base);
        int r_src = 0;
        float r_al = 0.0f;
        if (lane < n) {
            r_src = g_esrc[start + base + lane];
            r_al = g_al2s[r_src];
        }
        for (int j = 0; j < n; j++) {
            int src = __shfl_sync(0xffffffffu, r_src, j);
            float alv = __shfl_sync(0xffffffffu, r_al, j);
            float p = __expf(leaky(alv + ald));
            denom += p;
            const float* row = g_h2 + (size_t)src * NCLS;
            acc0 += p * row[lane];
            if (lane < 8) acc1 += p * row[32 + lane];
        }
    }
    float inv = 1.0f / (denom + 1e-16f);
    out[(size_t)dst * NCLS + lane] = acc0 * inv + b2[lane];
    if (lane < 8)
        out[(size_t)dst * NCLS + 32 + lane] = acc1 * inv + b2[32 + lane];
}

// ---------------- launch ----------------
extern "C" void kernel_launch(void* const* d_in, const int* in_sizes, int n_in,
                              void* d_out, int out_size) {
    const float* x        = (const float*)d_in[0];
    const int*   ei       = (const int*)  d_in[1];
    const float* W1       = (const float*)d_in[2];
    const float* att_src1 = (const float*)d_in[3];
    const float* att_dst1 = (const float*)d_in[4];
    const float* b1       = (const float*)d_in[5];
    const float* W2       = (const float*)d_in[6];
    const float* att_src2 = (const float*)d_in[7];
    const float* att_dst2 = (const float*)d_in[8];
    const float* b2       = (const float*)d_in[9];
    float* out = (float*)d_out;

    __half* p_h1h;
    float *p_h2, *p_out1, *p_al2s, *p_al2d;
    cudaGetSymbolAddress((void**)&p_h1h,  g_h1h);
    cudaGetSymbolAddress((void**)&p_h2,   g_h2);
    cudaGetSymbolAddress((void**)&p_out1, g_out1);
    cudaGetSymbolAddress((void**)&p_al2s, g_al2s);
    cudaGetSymbolAddress((void**)&p_al2d, g_al2d);

    // Side stream for CSR build (fork-join, graph-capture safe)
    cudaStream_t s2;
    cudaEvent_t evFork, evJoin;
    cudaStreamCreateWithFlags(&s2, cudaStreamNonBlocking);
    cudaEventCreateWithFlags(&evFork, cudaEventDisableTiming);
    cudaEventCreateWithFlags(&evJoin, cudaEventDisableTiming);

    // ---- fork: CSR build on s2, overlapped with GEMM1 on default stream ----
    cudaEventRecord(evFork, 0);
    cudaStreamWaitEvent(s2, evFork, 0);

    zero_deg_kernel<<<NB_SCAN, 256, 0, s2>>>();
    hist_kernel<<<(ETOT + 255) / 256, 256, 0, s2>>>(ei);
    scan1_kernel<<<NB_SCAN, 256, 0, s2>>>();
    scan2_kernel<<<1, 256, 0, s2>>>();
    scan3_kernel<<<NB_SCAN, 256, 0, s2>>>();
    scatter_kernel<<<(ETOT + 255) / 256, 256, 0, s2>>>(ei);
    cudaEventRecord(evJoin, s2);

    // 1. GEMM1 (tf32, fp16 output): h1 = x @ W1  [50000,512]x[512,256]
    {
        dim3 grid(D1 / 128, (NN + 127) / 128);
        tf32_gemm<128, 128, 4, D1, IN_CH, false, true><<<grid, 256>>>(
            x, W1, nullptr, p_h1h, NN, nullptr, nullptr, nullptr, nullptr);
    }

    // 2. attention dots layer 1 (reads fp16 h1)
    al1_kernel<<<(NN * HEADS + 255) / 256, 256>>>(att_src1, att_dst1);

    // ---- join: agg1 needs the CSR ----
    cudaStreamWaitEvent(0, evJoin, 0);

    // 3. fused softmax + aggregation + bias + ELU (layer 1)
    fused_agg1<<<(NN * 32 + 255) / 256, 256>>>(b1);

    // 4. GEMM2 (tf32) + fused al2 dots
    {
        dim3 grid(1, (NN + 255) / 256);
        tf32_gemm<256, 64, 8, NCLS, D1, true, false><<<grid, 256>>>(
            p_out1, W2, p_h2, nullptr, NN, att_src2, att_dst2, p_al2s, p_al2d);
    }

    // 5. fused softmax + aggregation + bias (layer 2) -> d_out
    fused_agg2<<<(NN * 32 + 255) / 256, 256>>>(b2, out);

    cudaEventDestroy(evFork);
    cudaEventDestroy(evJoin);
    cudaStreamDestroy(s2);
}

// round 8
// speedup vs baseline: 4.2705x; 1.1216x over previous
#include <cuda_runtime.h>
#include <cuda_fp16.h>
#include <math.h>
#include <stdint.h>

// Problem constants (fixed-shape problem)
#define NN      50000
#define EE      800000
#define ETOT    (EE + NN)      // self-loops appended
#define IN_CH   512
#define HID     32
#define HEADS   8
#define D1      (HID * HEADS)  // 256
#define NCLS    40
#define NEG_SLOPE 0.2f
#define NB_SCAN ((NN + 255) / 256)   // 196

// ---------------- scratch (device globals, no allocs allowed) ----------------
__device__ __align__(128) __half g_h1h[NN * D1];         // 25.6 MB (fp16 h1)
__device__ __align__(128) __half g_out1h[NN * D1];       // 25.6 MB (fp16 post-ELU)
__device__ __align__(128) float g_al_src[NN * HEADS];
__device__ __align__(128) float g_al_dst[NN * HEADS];
__device__ __align__(128) __half g_h2h[NN * NCLS];       // 4 MB (fp16 h2)
__device__ __align__(128) float g_al2s[NN];
__device__ __align__(128) float g_al2d[NN];
// CSR-by-dst
__device__ int g_deg[NN];
__device__ int g_off[NN];
__device__ int g_wpos[NN];
__device__ int g_esrc[ETOT];
__device__ int g_bsum[NB_SCAN];
__device__ int g_bsumx[NB_SCAN];

// ---------------- helpers ----------------
__device__ __forceinline__ float leaky(float x) {
    return x > 0.0f ? x : NEG_SLOPE * x;
}

__device__ __forceinline__ uint32_t h2_as_u32(__half2 h) {
    return *reinterpret_cast<uint32_t*>(&h);
}

__device__ __forceinline__ uint32_t f2tf32(float f) {
    uint32_t r;
    asm("cvt.rn.tf32.f32 %0, %1;" : "=r"(r) : "f"(f));
    return r;
}

__device__ __forceinline__ void mma_tf32(float c[4], uint32_t a0, uint32_t a1,
                                         uint32_t a2, uint32_t a3,
                                         uint32_t b0, uint32_t b1) {
    asm volatile(
        "mma.sync.aligned.m16n8k8.row.col.f32.tf32.tf32.f32 "
        "{%0,%1,%2,%3}, {%4,%5,%6,%7}, {%8,%9}, {%0,%1,%2,%3};\n"
        : "+f"(c[0]), "+f"(c[1]), "+f"(c[2]), "+f"(c[3])
        : "r"(a0), "r"(a1), "r"(a2), "r"(a3), "r"(b0), "r"(b1));
}

// =====================================================================
// tf32 tensor-core GEMM, register double-buffered.
// C[M,N] = A[M,K] @ B[K,N], row-major. 256 threads, warp tile 32x64.
// IN_FP16:  A is fp16 (converted exactly to tf32 path).
// OUT_FP16: store C as fp16.
// FUSE: 0 none; 1 per-row dots -> als/ald[row] (needs BN >= NCOLS);
//       2 per-head dots (32-col groups) -> als/ald[row*HEADS + head].
// =====================================================================
template <int BM, int BN, int WARPS_M, int NCOLS, int KTOT, int FUSE,
          bool OUT_FP16, bool IN_FP16>
__global__ __launch_bounds__(256)
void tf32_gemm(const void* __restrict__ Av, const float* __restrict__ B,
               float* __restrict__ Cf, __half* __restrict__ Ch, int M,
               const float* __restrict__ as2, const float* __restrict__ ad2,
               float* __restrict__ als, float* __restrict__ ald) {
    constexpr int APAD = 36;
    constexpr int BPAD = BN + 8;
    __shared__ uint32_t As[BM][APAD];
    __shared__ uint32_t Bs[32][BPAD];

    const float* Af = (const float*)Av;
    const __half* Ah = (const __half*)Av;

    const int tid = threadIdx.x;
    const int lane = tid & 31;
    const int warpId = tid >> 5;
    const int br = blockIdx.y;
    const int bc = blockIdx.x;

    const int wm = (warpId % WARPS_M) * 32;
    const int wn = (warpId / WARPS_M) * 64;
    const int g = lane >> 2;
    const int t = lane & 3;

    float acc[2][8][4];
#pragma unroll
    for (int mi = 0; mi < 2; mi++)
#pragma unroll
        for (int ni = 0; ni < 8; ni++)
#pragma unroll
            for (int r = 0; r < 4; r++) acc[mi][ni][r] = 0.0f;

    const int a_m = tid >> 3;
    const int a_k = (tid & 7) * 4;
    constexpr int AREG = BM / 32;
    constexpr int TPR = BN / 4;
    constexpr int BROWS = 256 / TPR;
    constexpr int BITER = 32 / BROWS;
    const int b_n = (tid % TPR) * 4;
    const int b_k = tid / TPR;

    float4 ra[AREG];
    float4 rb[BITER];

    auto loadA = [&](int r, int k0) -> float4 {
        int grow = br * BM + r * 32 + a_m;
        if (grow >= M) return make_float4(0.f, 0.f, 0.f, 0.f);
        if (IN_FP16) {
            uint2 u = *reinterpret_cast<const uint2*>(Ah + (size_t)grow * KTOT + k0 + a_k);
            float2 f0 = __half22float2(*reinterpret_cast<__half2*>(&u.x));
            float2 f1 = __half22float2(*reinterpret_cast<__half2*>(&u.y));
            return make_float4(f0.x, f0.y, f1.x, f1.y);
        } else {
            return *reinterpret_cast<const float4*>(Af + (size_t)grow * KTOT + k0 + a_k);
        }
    };

    // prologue: load chunk 0
#pragma unroll
    for (int r = 0; r < AREG; r++) ra[r] = loadA(r, 0);
#pragma unroll
    for (int r = 0; r < BITER; r++) {
        int gn = bc * BN + b_n;
        rb[r] = make_float4(0.f, 0.f, 0.f, 0.f);
        if (gn < NCOLS)
            rb[r] = *reinterpret_cast<const float4*>(B + (size_t)(r * BROWS + b_k) * NCOLS + gn);
    }

    for (int k0 = 0; k0 < KTOT; k0 += 32) {
#pragma unroll
        for (int r = 0; r < AREG; r++) {
            uint4 u;
            u.x = f2tf32(ra[r].x); u.y = f2tf32(ra[r].y);
            u.z = f2tf32(ra[r].z); u.w = f2tf32(ra[r].w);
            *reinterpret_cast<uint4*>(&As[r * 32 + a_m][a_k]) = u;
        }
#pragma unroll
        for (int r = 0; r < BITER; r++) {
            uint4 u;
            u.x = f2tf32(rb[r].x); u.y = f2tf32(rb[r].y);
            u.z = f2tf32(rb[r].z); u.w = f2tf32(rb[r].w);
            *reinterpret_cast<uint4*>(&Bs[r * BROWS + b_k][b_n]) = u;
        }
        __syncthreads();

        if (k0 + 32 < KTOT) {
#pragma unroll
            for (int r = 0; r < AREG; r++) ra[r] = loadA(r, k0 + 32);
#pragma unroll
            for (int r = 0; r < BITER; r++) {
                int gn = bc * BN + b_n;
                rb[r] = make_float4(0.f, 0.f, 0.f, 0.f);
                if (gn < NCOLS)
                    rb[r] = *reinterpret_cast<const float4*>(
                        B + (size_t)(k0 + 32 + r * BROWS + b_k) * NCOLS + gn);
            }
        }

#pragma unroll
        for (int ks = 0; ks < 4; ks++) {
            const int kk = ks * 8;
            uint32_t a[2][4];
#pragma unroll
            for (int mi = 0; mi < 2; mi++) {
                int m0 = wm + mi * 16 + g;
                a[mi][0] = As[m0][kk + t];
                a[mi][1] = As[m0 + 8][kk + t];
                a[mi][2] = As[m0][kk + t + 4];
                a[mi][3] = As[m0 + 8][kk + t + 4];
            }
#pragma unroll
            for (int ni = 0; ni < 8; ni++) {
                int n0 = wn + ni * 8 + g;
                uint32_t b0 = Bs[kk + t][n0];
                uint32_t b1 = Bs[kk + t + 4][n0];
                mma_tf32(acc[0][ni], a[0][0], a[0][1], a[0][2], a[0][3], b0, b1);
                mma_tf32(acc[1][ni], a[1][0], a[1][1], a[1][2], a[1][3], b0, b1);
            }
        }
        __syncthreads();
    }

    // ---- epilogue: store C ----
#pragma unroll
    for (int mi = 0; mi < 2; mi++) {
        int row0 = br * BM + wm + mi * 16 + g;
        int row1 = row0 + 8;
#pragma unroll
        for (int ni = 0; ni < 8; ni++) {
            int col = bc * BN + wn + ni * 8 + 2 * t;
            if (col < NCOLS) {
                if (OUT_FP16) {
                    if (row0 < M)
                        *reinterpret_cast<__half2*>(Ch + (size_t)row0 * NCOLS + col) =
                            __float22half2_rn(make_float2(acc[mi][ni][0], acc[mi][ni][1]));
                    if (row1 < M)
                        *reinterpret_cast<__half2*>(Ch + (size_t)row1 * NCOLS + col) =
                            __float22half2_rn(make_float2(acc[mi][ni][2], acc[mi][ni][3]));
                } else {
                    if (row0 < M) {
                        float2 v = make_float2(acc[mi][ni][0], acc[mi][ni][1]);
                        *reinterpret_cast<float2*>(Cf + (size_t)row0 * NCOLS + col) = v;
                    }
                    if (row1 < M) {
                        float2 v = make_float2(acc[mi][ni][2], acc[mi][ni][3]);
                        *reinterpret_cast<float2*>(Cf + (size_t)row1 * NCOLS + col) = v;
                    }
                }
            }
        }
    }

    // ---- FUSE==1: per-row attention dots (layer 2) ----
    if (FUSE == 1) {
#pragma unroll
        for (int mi = 0; mi < 2; mi++) {
            float ps0 = 0.f, ps1 = 0.f, pd0 = 0.f, pd1 = 0.f;
#pragma unroll
            for (int ni = 0; ni < 8; ni++) {
                int col = wn + ni * 8 + 2 * t;
                if (col < NCOLS) {
                    float a0 = as2[col], a1 = as2[col + 1];
                    float d0 = ad2[col], d1 = ad2[col + 1];
                    ps0 += acc[mi][ni][0] * a0 + acc[mi][ni][1] * a1;
                    ps1 += acc[mi][ni][2] * a0 + acc[mi][ni][3] * a1;
                    pd0 += acc[mi][ni][0] * d0 + acc[mi][ni][1] * d1;
                    pd1 += acc[mi][ni][2] * d0 + acc[mi][ni][3] * d1;
                }
            }
#pragma unroll
            for (int off = 1; off < 4; off <<= 1) {
                ps0 += __shfl_xor_sync(0xffffffffu, ps0, off);
                ps1 += __shfl_xor_sync(0xffffffffu, ps1, off);
                pd0 += __shfl_xor_sync(0xffffffffu, pd0, off);
                pd1 += __shfl_xor_sync(0xffffffffu, pd1, off);
            }
            if (t == 0) {
                int row0 = br * BM + wm + mi * 16 + g;
                int row1 = row0 + 8;
                if (row0 < M) { als[row0] = ps0; ald[row0] = pd0; }
                if (row1 < M) { als[row1] = ps1; ald[row1] = pd1; }
            }
        }
    }

    // ---- FUSE==2: per-head attention dots (layer 1, 32-col head groups) ----
    if (FUSE == 2) {
#pragma unroll
        for (int mi = 0; mi < 2; mi++) {
#pragma unroll
            for (int hl = 0; hl < 2; hl++) {
                float ps0 = 0.f, ps1 = 0.f, pd0 = 0.f, pd1 = 0.f;
#pragma unroll
                for (int nq = 0; nq < 4; nq++) {
                    int ni = hl * 4 + nq;
                    int gcol = bc * BN + wn + ni * 8 + 2 * t;
                    float a0 = as2[gcol], a1 = as2[gcol + 1];
                    float d0 = ad2[gcol], d1 = ad2[gcol + 1];
                    ps0 += acc[mi][ni][0] * a0 + acc[mi][ni][1] * a1;
                    ps1 += acc[mi][ni][2] * a0 + acc[mi][ni][3] * a1;
                    pd0 += acc[mi][ni][0] * d0 + acc[mi][ni][1] * d1;
                    pd1 += acc[mi][ni][2] * d0 + acc[mi][ni][3] * d1;
                }
#pragma unroll
                for (int off = 1; off < 4; off <<= 1) {
                    ps0 += __shfl_xor_sync(0xffffffffu, ps0, off);
                    ps1 += __shfl_xor_sync(0xffffffffu, ps1, off);
                    pd0 += __shfl_xor_sync(0xffffffffu, pd0, off);
                    pd1 += __shfl_xor_sync(0xffffffffu, pd1, off);
                }
                if (t == 0) {
                    int head = ((bc * BN + wn) >> 5) + hl;
                    int row0 = br * BM + wm + mi * 16 + g;
                    int row1 = row0 + 8;
                    if (row0 < M) {
                        als[(size_t)row0 * HEADS + head] = ps0;
                        ald[(size_t)row0 * HEADS + head] = pd0;
                    }
                    if (row1 < M) {
                        als[(size_t)row1 * HEADS + head] = ps1;
                        ald[(size_t)row1 * HEADS + head] = pd1;
                    }
                }
            }
        }
    }
}

// ================= CSR build =================
__global__ void zero_deg_kernel() {
    int i = blockIdx.x * blockDim.x + threadIdx.x;
    if (i < NN) g_deg[i] = 0;
}

__global__ void hist_kernel(const int* __restrict__ ei) {
    int e = blockIdx.x * blockDim.x + threadIdx.x;
    if (e >= ETOT) return;
    int dst = (e < EE) ? ei[EE + e] : e - EE;
    atomicAdd(&g_deg[dst], 1);
}

__global__ void scan1_kernel() {
    __shared__ int s[256];
    int i = blockIdx.x * 256 + threadIdx.x;
    int v = (i < NN) ? g_deg[i] : 0;
    s[threadIdx.x] = v;
    __syncthreads();
#pragma unroll
    for (int d = 1; d < 256; d <<= 1) {
        int t = (threadIdx.x >= d) ? s[threadIdx.x - d] : 0;
        __syncthreads();
        s[threadIdx.x] += t;
        __syncthreads();
    }
    if (i < NN) g_off[i] = s[threadIdx.x] - v;   // exclusive
    if (threadIdx.x == 255) g_bsum[blockIdx.x] = s[255];
}

__global__ void scan2_kernel() {
    __shared__ int s[256];
    int v = (threadIdx.x < NB_SCAN) ? g_bsum[threadIdx.x] : 0;
    s[threadIdx.x] = v;
    __syncthreads();
#pragma unroll
    for (int d = 1; d < 256; d <<= 1) {
        int t = (threadIdx.x >= d) ? s[threadIdx.x - d] : 0;
        __syncthreads();
        s[threadIdx.x] += t;
        __syncthreads();
    }
    if (threadIdx.x < NB_SCAN) g_bsumx[threadIdx.x] = s[threadIdx.x] - v;
}

__global__ void scan3_kernel() {
    int i = blockIdx.x * 256 + threadIdx.x;
    if (i < NN) {
        int o = g_off[i] + g_bsumx[blockIdx.x];
        g_off[i] = o;
        g_wpos[i] = o;
    }
}

__global__ void scatter_kernel(const int* __restrict__ ei) {
    int e = blockIdx.x * blockDim.x + threadIdx.x;
    if (e >= ETOT) return;
    int src, dst;
    if (e < EE) { src = ei[e]; dst = ei[EE + e]; }
    else        { src = dst = e - EE; }
    int pos = atomicAdd(&g_wpos[dst], 1);
    g_esrc[pos] = src;
}

// ================= fused softmax + aggregation, layer 1 =================
// One warp per dst. Lane owns 8 consecutive channels (head = lane>>2).
// h1 gathered fp16 (16B/lane/edge), fp32 accumulate, fp16 out1.
__global__ __launch_bounds__(256)
void fused_agg1(const float* __restrict__ b1) {
    int dst = (blockIdx.x * 256 + threadIdx.x) >> 5;
    int lane = threadIdx.x & 31;
    if (dst >= NN) return;
    int head = lane >> 2;
    float ald = g_al_dst[(size_t)dst * 8 + head];
    int start = g_off[dst];
    int deg = g_deg[dst];

    float acc[8];
#pragma unroll
    for (int j = 0; j < 8; j++) acc[j] = 0.0f;
    float denom = 0.0f;

    for (int base = 0; base < deg; base += 32) {
        int n = min(32, deg - base);
        int r_src = (lane < n) ? g_esrc[start + base + lane] : 0;
        for (int j = 0; j < n; j++) {
            int src = __shfl_sync(0xffffffffu, r_src, j);
            float p = __expf(leaky(g_al_src[(size_t)src * 8 + head] + ald));
            denom += p;
            uint4 u = *reinterpret_cast<const uint4*>(
                g_h1h + (size_t)src * D1 + lane * 8);
            float2 f0 = __half22float2(*reinterpret_cast<__half2*>(&u.x));
            float2 f1 = __half22float2(*reinterpret_cast<__half2*>(&u.y));
            float2 f2 = __half22float2(*reinterpret_cast<__half2*>(&u.z));
            float2 f3 = __half22float2(*reinterpret_cast<__half2*>(&u.w));
            acc[0] += p * f0.x; acc[1] += p * f0.y;
            acc[2] += p * f1.x; acc[3] += p * f1.y;
            acc[4] += p * f2.x; acc[5] += p * f2.y;
            acc[6] += p * f3.x; acc[7] += p * f3.y;
        }
    }

    float inv = 1.0f / (denom + 1e-16f);
    float o[8];
#pragma unroll
    for (int j = 0; j < 8; j++) {
        float v = acc[j] * inv + b1[lane * 8 + j];
        o[j] = v > 0.0f ? v : expm1f(v);       // fused ELU
    }
    uint4 st;
    st.x = h2_as_u32(__float22half2_rn(make_float2(o[0], o[1])));
    st.y = h2_as_u32(__float22half2_rn(make_float2(o[2], o[3])));
    st.z = h2_as_u32(__float22half2_rn(make_float2(o[4], o[5])));
    st.w = h2_as_u32(__float22half2_rn(make_float2(o[6], o[7])));
    *reinterpret_cast<uint4*>(g_out1h + (size_t)dst * D1 + lane * 8) = st;
}

// ================= fused softmax + aggregation, layer 2 =================
// One warp per dst. Lanes 0..19 each own channels {2l, 2l+1} (one half2 load).
__global__ __launch_bounds__(256)
void fused_agg2(const float* __restrict__ b2, float* __restrict__ out) {
    int dst = (blockIdx.x * 256 + threadIdx.x) >> 5;
    int lane = threadIdx.x & 31;
    if (dst >= NN) return;
    float ald = g_al2d[dst];
    int start = g_off[dst];
    int deg = g_deg[dst];

    float acc0 = 0.0f, acc1 = 0.0f, denom = 0.0f;
    for (int base = 0; base < deg; base += 32) {
        int n = min(32, deg - base);
        int r_src = 0;
        float r_al = 0.0f;
        if (lane < n) {
            r_src = g_esrc[start + base + lane];
            r_al = g_al2s[r_src];
        }
        for (int j = 0; j < n; j++) {
            int src = __shfl_sync(0xffffffffu, r_src, j);
            float alv = __shfl_sync(0xffffffffu, r_al, j);
            float p = __expf(leaky(alv + ald));
            denom += p;
            if (lane < 20) {
                uint32_t hv = *reinterpret_cast<const uint32_t*>(
                    g_h2h + (size_t)src * NCLS + 2 * lane);
                float2 f = __half22float2(*reinterpret_cast<__half2*>(&hv));
                acc0 += p * f.x;
                acc1 += p * f.y;
            }
        }
    }
    if (lane < 20) {
        float inv = 1.0f / (denom + 1e-16f);
        float2 v = make_float2(acc0 * inv + b2[2 * lane],
                               acc1 * inv + b2[2 * lane + 1]);
        *reinterpret_cast<float2*>(out + (size_t)dst * NCLS + 2 * lane) = v;
    }
}

// ---------------- launch ----------------
extern "C" void kernel_launch(void* const* d_in, const int* in_sizes, int n_in,
                              void* d_out, int out_size) {
    const float* x        = (const float*)d_in[0];
    const int*   ei       = (const int*)  d_in[1];
    const float* W1       = (const float*)d_in[2];
    const float* att_src1 = (const float*)d_in[3];
    const float* att_dst1 = (const float*)d_in[4];
    const float* b1       = (const float*)d_in[5];
    const float* W2       = (const float*)d_in[6];
    const float* att_src2 = (const float*)d_in[7];
    const float* att_dst2 = (const float*)d_in[8];
    const float* b2       = (const float*)d_in[9];
    float* out = (float*)d_out;

    __half *p_h1h, *p_out1h, *p_h2h;
    float *p_al2s, *p_al2d, *p_als, *p_ald;
    cudaGetSymbolAddress((void**)&p_h1h,   g_h1h);
    cudaGetSymbolAddress((void**)&p_out1h, g_out1h);
    cudaGetSymbolAddress((void**)&p_h2h,   g_h2h);
    cudaGetSymbolAddress((void**)&p_al2s,  g_al2s);
    cudaGetSymbolAddress((void**)&p_al2d,  g_al2d);
    cudaGetSymbolAddress((void**)&p_als,   g_al_src);
    cudaGetSymbolAddress((void**)&p_ald,   g_al_dst);

    // Side stream for CSR build (fork-join, graph-capture safe)
    cudaStream_t s2;
    cudaEvent_t evFork, evJoin;
    cudaStreamCreateWithFlags(&s2, cudaStreamNonBlocking);
    cudaEventCreateWithFlags(&evFork, cudaEventDisableTiming);
    cudaEventCreateWithFlags(&evJoin, cudaEventDisableTiming);

    // ---- fork: CSR build on s2, overlapped with GEMM1 ----
    cudaEventRecord(evFork, 0);
    cudaStreamWaitEvent(s2, evFork, 0);

    zero_deg_kernel<<<NB_SCAN, 256, 0, s2>>>();
    hist_kernel<<<(ETOT + 255) / 256, 256, 0, s2>>>(ei);
    scan1_kernel<<<NB_SCAN, 256, 0, s2>>>();
    scan2_kernel<<<1, 256, 0, s2>>>();
    scan3_kernel<<<NB_SCAN, 256, 0, s2>>>();
    scatter_kernel<<<(ETOT + 255) / 256, 256, 0, s2>>>(ei);
    cudaEventRecord(evJoin, s2);

    // 1. GEMM1 (tf32, fp16 out, fused per-head al1 dots from fp32 acc)
    {
        dim3 grid(D1 / 128, (NN + 127) / 128);
        tf32_gemm<128, 128, 4, D1, IN_CH, 2, true, false><<<grid, 256>>>(
            x, W1, nullptr, p_h1h, NN, att_src1, att_dst1, p_als, p_ald);
    }

    // ---- join: agg1 needs the CSR ----
    cudaStreamWaitEvent(0, evJoin, 0);

    // 2. fused softmax + aggregation + bias + ELU (layer 1), fp16 out1
    fused_agg1<<<(NN * 32 + 255) / 256, 256>>>(b1);

    // 3. GEMM2 (tf32, fp16 in/out, fused per-row al2 dots)
    {
        dim3 grid(1, (NN + 255) / 256);
        tf32_gemm<256, 64, 8, NCLS, D1, 1, true, true><<<grid, 256>>>(
            p_out1h, W2, nullptr, p_h2h, NN, att_src2, att_dst2, p_al2s, p_al2d);
    }

    // 4. fused softmax + aggregation + bias (layer 2) -> d_out
    fused_agg2<<<(NN * 32 + 255) / 256, 256>>>(b2, out);

    cudaEventDestroy(evFork);
    cudaEventDestroy(evJoin);
    cudaStreamDestroy(s2);
}